// round 14
// baseline (speedup 1.0000x reference)
#include <cuda_runtime.h>
#include <cuda_bf16.h>

#define BB 8
#define HH 256
#define WW 256
#define NPIXTOT (BB*HH*WW)   // 2^19

// ---------------- bf16 helpers ---------------------------------------------
__device__ __forceinline__ unsigned bf2(float lo, float hi) {
    __nv_bfloat162 h = __floats2bfloat162_rn(lo, hi);
    return *(unsigned*)&h;
}
__device__ __forceinline__ float2 unbf2(unsigned w) {
    return __bfloat1622float2(*(__nv_bfloat162*)&w);
}
__device__ __forceinline__ void mma_bf16(float* c,
    unsigned a0, unsigned a1, unsigned a2, unsigned a3,
    unsigned b0, unsigned b1)
{
    asm("mma.sync.aligned.m16n8k16.row.col.f32.bf16.bf16.f32 "
        "{%0,%1,%2,%3}, {%4,%5,%6,%7}, {%8,%9}, {%0,%1,%2,%3};"
        : "+f"(c[0]), "+f"(c[1]), "+f"(c[2]), "+f"(c[3])
        : "r"(a0), "r"(a1), "r"(a2), "r"(a3), "r"(b0), "r"(b1));
}

// Pair-interleaved k layout: within each 16-channel block, word w (0..7)
// holds channel pair q = (w>>1) + (w&1)*4. Pair q -> word (q&3)*2 + (q>>2).
// Images are stored DIRECTLY in this order so staging is a raw copy.

// ---------------- scratch (device globals; no allocation allowed) ----------
__device__ unsigned g_c0_w[2ull * NPIXTOT * 16];   // conv0 out, bf16 pairs
__device__ float    g_flowch[2ull * NPIXTOT * 2];
__device__ unsigned g_img_w[2ull * NPIXTOT * 16];  // bf16 images (interleaved)
__device__ unsigned g_warp_w[2ull * NPIXTOT * 16]; // warped images (interleaved)

#define PW0 40
#define PW1 24
#define PWF 40
#define WPW_N0 (9*32*PW0)
#define WPW_N1 (9*64*PW1)
#define WPW_F2 (64*PWF)
#define WPW_F3 (16*PWF)
#define WPW_PER (WPW_N0 + WPW_N1 + WPW_F2 + WPW_F3)
__device__ unsigned g_wpack[2 * WPW_PER];
#define BP_PER 256
__device__ float g_bpack[2 * BP_PER];

// ---------------- image prepack: fp32 NHWC -> bf16 pairs (interleaved) -----
__global__ __launch_bounds__(256) void imgpack_kernel(
    const float* __restrict__ i1, const float* __restrict__ i2,
    unsigned* __restrict__ dst)
{
    int idx = blockIdx.x * blockDim.x + threadIdx.x;   // 2 * NPIXTOT * 16
    const float* src = (idx < NPIXTOT * 16) ? i1 : i2;
    int jj = idx & (NPIXTOT * 16 - 1);
    int pix = jj >> 4, j = jj & 15;
    int block = j >> 3, ww = j & 7;
    int q = (ww >> 1) + ((ww & 1) << 2);
    // channel pair index within pixel = block*8 + q
    float2 v = ((const float2*)src)[(size_t)pix * 16 + block * 8 + q];
    dst[idx] = bf2(v.x, v.y);
}

// ---------------- bilinear warp, bf16 -> bf16 (once per pixel) -------------
__global__ __launch_bounds__(256) void warpbf_kernel(
    const unsigned* __restrict__ imgw,
    const float* __restrict__ flow12, const float* __restrict__ flow21,
    unsigned* __restrict__ warpw)
{
    int idx = blockIdx.x * blockDim.x + threadIdx.x;   // 2 * NPIXTOT * 2
    int half = idx & 1;
    int pix  = (idx >> 1) & (NPIXTOT - 1);
    int dir  = idx >> 20;
    const float* flow = dir ? flow21 : flow12;
    const unsigned* srcw = imgw + (size_t)dir * NPIXTOT * 16;

    int x = pix & (WW - 1);
    int y = (pix >> 8) & (HH - 1);
    int b = pix >> 16;
    float2 f = ((const float2*)flow)[pix];
    float qy = (float)y - f.x;
    float qx = (float)x - f.y;
    float fy = fminf(fmaxf(floorf(qy), 0.f), (float)(HH - 2));
    float fx = fminf(fmaxf(floorf(qx), 0.f), (float)(WW - 2));
    float ay = fminf(fmaxf(qy - fy, 0.f), 1.f);
    float ax = fminf(fmaxf(qx - fx, 0.f), 1.f);
    int iy = (int)fy, ix = (int)fx;
    const unsigned* sp = srcw + (size_t)((b * HH + iy) * WW + ix) * 16 + half * 8;

    unsigned tl[8], tr[8], bl[8], br[8], o[8];
    *(uint4*)tl = *(const uint4*)sp;
    *(uint4*)(tl + 4) = *(const uint4*)(sp + 4);
    *(uint4*)tr = *(const uint4*)(sp + 16);
    *(uint4*)(tr + 4) = *(const uint4*)(sp + 20);
    *(uint4*)bl = *(const uint4*)(sp + WW * 16);
    *(uint4*)(bl + 4) = *(const uint4*)(sp + WW * 16 + 4);
    *(uint4*)br = *(const uint4*)(sp + WW * 16 + 16);
    *(uint4*)(br + 4) = *(const uint4*)(sp + WW * 16 + 20);
    #pragma unroll
    for (int j = 0; j < 8; j++) {
        float2 a = unbf2(tl[j]), bb = unbf2(tr[j]);
        float2 c = unbf2(bl[j]), d = unbf2(br[j]);
        float tx = a.x + ax * (bb.x - a.x);
        float ty = a.y + ax * (bb.y - a.y);
        float ux = c.x + ax * (d.x - c.x);
        float uy = c.y + ax * (d.y - c.y);
        o[j] = bf2(tx + ay * (ux - tx), ty + ay * (uy - ty));
    }
    unsigned* dp = warpw + (size_t)dir * NPIXTOT * 16 + (size_t)pix * 16 + half * 8;
    *(uint4*)dp = *(uint4*)o;
    *(uint4*)(dp + 4) = *(uint4*)(o + 4);
}

// ---------------- weight prepack (bf16 pairs, final smem images) -----------
__global__ void prepack_kernel(
    const float* __restrict__ c0d0, const float* __restrict__ c1d0,
    const float* __restrict__ w2d0, const float* __restrict__ w3d0,
    const float* __restrict__ c0d1, const float* __restrict__ c1d1,
    const float* __restrict__ w2d1, const float* __restrict__ w3d1,
    unsigned* __restrict__ dst)
{
    int i = blockIdx.x * blockDim.x + threadIdx.x;
    if (i >= 2 * WPW_PER) return;
    int dir = (i >= WPW_PER);
    int j = i - dir * WPW_PER;
    const float* w;
    int CIN, COUT, PW;
    if (j < WPW_N0) {
        w = dir ? c0d1 : c0d0; CIN = 64; COUT = 32; PW = PW0;
    } else if (j < WPW_N0 + WPW_N1) {
        j -= WPW_N0; w = dir ? c1d1 : c1d0; CIN = 32; COUT = 64; PW = PW1;
    } else if (j < WPW_N0 + WPW_N1 + WPW_F2) {
        j -= WPW_N0 + WPW_N1; w = dir ? w2d1 : w2d0; CIN = 64; COUT = 64; PW = PWF;
    } else {
        j -= WPW_N0 + WPW_N1 + WPW_F2; w = dir ? w3d1 : w3d0; CIN = 64; COUT = 16; PW = PWF;
    }
    int word = j % PW;
    int r    = j / PW;
    int oc   = r % COUT;
    int tap  = r / COUT;
    float lo = 0.f, hi = 0.f;
    int block = word >> 3, ww = word & 7;
    int q  = (ww >> 1) + (ww & 1) * 4;
    int ch = block * 16 + 2 * q;
    if (ch < CIN) {
        lo = w[(tap * CIN + ch) * COUT + oc];
        hi = w[(tap * CIN + ch + 1) * COUT + oc];
    }
    dst[i] = bf2(lo, hi);
}

__global__ void biaspack_kernel(
    const float* __restrict__ b0d0, const float* __restrict__ b1d0,
    const float* __restrict__ b2d0, const float* __restrict__ b3d0,
    const float* __restrict__ w4d0, const float* __restrict__ b4d0,
    const float* __restrict__ b0d1, const float* __restrict__ b1d1,
    const float* __restrict__ b2d1, const float* __restrict__ b3d1,
    const float* __restrict__ w4d1, const float* __restrict__ b4d1,
    float* __restrict__ dst)
{
    int i = threadIdx.x;
    int dir = blockIdx.x;
    const float* srcs[6] = {
        dir ? b0d1 : b0d0, dir ? b1d1 : b1d0, dir ? b2d1 : b2d0,
        dir ? b3d1 : b3d0, dir ? w4d1 : w4d0, dir ? b4d1 : b4d0 };
    const int offs[7] = {0, 32, 96, 160, 176, 208, 210};
    float v = 0.f;
    #pragma unroll
    for (int s = 0; s < 6; s++)
        if (i >= offs[s] && i < offs[s + 1]) v = srcs[s][i - offs[s]];
    dst[dir * BP_PER + i] = v;
}

// ---------------- bilinear 4-channel gather helper (fp32 src) ---------------
__device__ __forceinline__ float4 bilin4(const float4* s4, int base,
                                         float ay, float ax)
{
    float4 tl = s4[base];
    float4 tr = s4[base + 8];
    float4 bl = s4[base + WW * 8];
    float4 br = s4[base + WW * 8 + 8];
    float4 top, bot, r;
    top.x = tl.x + ax * (tr.x - tl.x); top.y = tl.y + ax * (tr.y - tl.y);
    top.z = tl.z + ax * (tr.z - tl.z); top.w = tl.w + ax * (tr.w - tl.w);
    bot.x = bl.x + ax * (br.x - bl.x); bot.y = bl.y + ax * (br.y - bl.y);
    bot.z = bl.z + ax * (br.z - bl.z); bot.w = bl.w + ax * (br.w - bl.w);
    r.x = top.x + ay * (bot.x - top.x); r.y = top.y + ay * (bot.y - top.y);
    r.z = top.z + ay * (bot.z - top.z); r.w = top.w + ay * (bot.w - top.w);
    return r;
}

// ---------------- conv0: 64->32, tile 16x16, pure-copy staging -------------
__global__ __launch_bounds__(256, 2) void conv0_tc_kernel(
    const unsigned* __restrict__ imgw, const unsigned* __restrict__ warpw,
    const unsigned* __restrict__ wpackg, const float* __restrict__ bpackg,
    unsigned* __restrict__ c0wg)
{
    constexpr int COUT = 32;
    constexpr int TX = 16, TY = 16;
    constexpr int TW = TX + 2, TH = TY + 2;
    constexpr int PW = PW0;
    constexpr int NT = COUT / 8;     // 4
    constexpr int KC = 4;
    constexpr int TILE_W = TH * TW * PW;
    constexpr int WN = WPW_N0;

    extern __shared__ unsigned smw[];
    unsigned* tile = smw;
    unsigned* sw   = smw + TILE_W;
    float*    sb   = (float*)(sw + WN);

    const int dir = blockIdx.z >> 3;
    const int b   = blockIdx.z & 7;
    const unsigned* otherw = imgw + (size_t)(1 - dir) * NPIXTOT * 16;
    const unsigned* warped = warpw + (size_t)dir * NPIXTOT * 16;
    const unsigned* wpack = wpackg + (size_t)dir * WPW_PER;
    const float* bias = bpackg + dir * BP_PER;
    unsigned* outw = c0wg + (size_t)dir * NPIXTOT * 16;

    const int bx = blockIdx.x * TX;
    const int by = blockIdx.y * TY;
    const int tid = threadIdx.x;

    {
        const uint4* s4 = (const uint4*)wpack;
        uint4* d4 = (uint4*)sw;
        #pragma unroll 4
        for (int i = tid; i < WN / 4; i += 256) d4[i] = s4[i];
        if (tid < COUT) sb[tid] = bias[tid];
    }
    // staging: PURE uint4 copies. words 0-15 <- other, 16-31 <- warped.
    for (int i = tid; i < TH * TW * 8; i += 256) {
        int q = i & 7;                 // uint4 index within pixel (0..7)
        int p = i >> 3;
        int xx = p % TW;
        int yy = p / TW;
        int gx = bx + xx - 1;
        int gy = by + yy - 1;
        uint4 v = make_uint4(0, 0, 0, 0);
        if (gx >= 0 && gx < WW && gy >= 0 && gy < HH) {
            size_t pix = (size_t)((b * HH + gy) * WW + gx);
            const unsigned* src = (q < 4) ? otherw : warped;
            v = *(const uint4*)(src + pix * 16 + (q & 3) * 4);
        }
        *(uint4*)(tile + p * PW + q * 4) = v;
    }
    __syncthreads();

    const int lane = tid & 31;
    const int w    = tid >> 5;     // warp = rows 2w, 2w+1
    const int g = lane >> 2;
    const int t = lane & 3;

    float acc0[NT][4], acc1[NT][4];
    #pragma unroll
    for (int nt = 0; nt < NT; nt++)
        #pragma unroll
        for (int k = 0; k < 4; k++) { acc0[nt][k] = 0.f; acc1[nt][k] = 0.f; }

    #pragma unroll 1
    for (int tap = 0; tap < 9; tap++) {
        const int dy = tap / 3, dx = tap % 3;
        const unsigned* a0b = tile + ((2 * w + dy) * TW + dx) * PW;
        const unsigned* a1b = a0b + TW * PW;
        const unsigned* wb = sw + tap * COUT * PW;
        #pragma unroll
        for (int kb = 0; kb < KC; kb++) {
            const int ko = kb * 8 + 2 * t;
            uint2 ra0 = *(const uint2*)(a0b + g * PW + ko);
            uint2 rb0 = *(const uint2*)(a0b + (g + 8) * PW + ko);
            uint2 ra1 = *(const uint2*)(a1b + g * PW + ko);
            uint2 rb1 = *(const uint2*)(a1b + (g + 8) * PW + ko);
            #pragma unroll
            for (int nt = 0; nt < NT; nt++) {
                uint2 wv = *(const uint2*)(wb + (nt * 8 + g) * PW + ko);
                mma_bf16(acc0[nt], ra0.x, rb0.x, ra0.y, rb0.y, wv.x, wv.y);
                mma_bf16(acc1[nt], ra1.x, rb1.x, ra1.y, rb1.y, wv.x, wv.y);
            }
        }
    }

    #pragma unroll
    for (int rr = 0; rr < 2; rr++) {
        const int gy = by + 2 * w + rr;
        float (*acc)[4] = rr ? acc1 : acc0;
        size_t pix0 = (size_t)((b * HH + gy) * WW + bx + g);
        unsigned* o0 = outw + pix0 * 16;
        unsigned* o1 = o0 + 8 * 16;
        #pragma unroll
        for (int nt = 0; nt < NT; nt++) {
            int oc = nt * 8 + 2 * t;
            int pairidx = nt * 4 + t;
            int word = (pairidx >> 3) * 8 + ((pairidx & 7) & 3) * 2 + ((pairidx & 7) >> 2);
            float bi0 = sb[oc], bi1 = sb[oc + 1];
            o0[word] = bf2(fmaxf(acc[nt][0] + bi0, 0.f), fmaxf(acc[nt][1] + bi1, 0.f));
            o1[word] = bf2(fmaxf(acc[nt][2] + bi0, 0.f), fmaxf(acc[nt][3] + bi1, 0.f));
        }
    }
}

// ---------------- MEGA: conv1 + 1x1 chain + flow add + final warp ----------
__global__ __launch_bounds__(256, 2) void conv1_mega_kernel(
    const unsigned* __restrict__ c0wg,
    const float* __restrict__ input_1, const float* __restrict__ input_2,
    const float* __restrict__ flow12, const float* __restrict__ flow21,
    const unsigned* __restrict__ wpackg, const float* __restrict__ bpackg,
    float* __restrict__ outAll, float* __restrict__ flowchg)
{
    constexpr int COUT = 64;
    constexpr int TX = 16, TY = 16;
    constexpr int TW = TX + 2, TH = TY + 2;
    constexpr int PW = PW1;
    constexpr int NT = COUT / 8;
    constexpr int KC = 2;
    constexpr int TILE_W = TH * TW * PW;

    extern __shared__ unsigned smw[];
    unsigned* tile = smw;
    unsigned* sw1  = smw + TILE_W;
    unsigned* sw2  = sw1 + WPW_N1;
    unsigned* sw3  = sw2 + WPW_F2;
    float*    sbf  = (float*)(sw3 + WPW_F3);

    const int dir = blockIdx.z >> 3;
    const int b   = blockIdx.z & 7;
    const float* srcimg = dir ? input_2 : input_1;
    const float* flow = dir ? flow21 : flow12;
    const unsigned* wbase = wpackg + (size_t)dir * WPW_PER;
    const unsigned* in = c0wg + (size_t)dir * NPIXTOT * 16;
    float* flowch = flowchg + (size_t)dir * NPIXTOT * 2;
    float* outWarped = outAll + (size_t)dir * NPIXTOT * 32;

    float* sb1  = sbf + 32;
    float* sb2  = sbf + 96;
    float* sb3  = sbf + 160;
    float* sw4f = sbf + 176;
    float* sb4  = sbf + 208;

    const int bx = blockIdx.x * TX;
    const int by = blockIdx.y * TY;
    const int tid = threadIdx.x;

    {
        const uint4* s1 = (const uint4*)(wbase + WPW_N0);
        uint4* d1 = (uint4*)sw1;
        #pragma unroll 4
        for (int i = tid; i < (WPW_N1 + WPW_F2 + WPW_F3) / 4; i += 256) d1[i] = s1[i];
        sbf[tid] = bpackg[dir * BP_PER + tid];
    }
    for (int i = tid; i < TH * TW * KC; i += 256) {
        int kb = i & 1;
        int p  = i >> 1;
        int xx = p % TW;
        int yy = p / TW;
        int gx = bx + xx - 1;
        int gy = by + yy - 1;
        uint4 w0 = make_uint4(0, 0, 0, 0), w1 = w0;
        if (gx >= 0 && gx < WW && gy >= 0 && gy < HH) {
            size_t pix = (size_t)((b * HH + gy) * WW + gx);
            const uint4* s = (const uint4*)(in + pix * 16 + kb * 8);
            w0 = s[0]; w1 = s[1];
        }
        uint4* d = (uint4*)(tile + p * PW + kb * 8);
        d[0] = w0;
        d[1] = w1;
    }
    __syncthreads();

    const int lane = tid & 31;
    const int w    = tid >> 5;
    const int g = lane >> 2;
    const int t = lane & 3;

    float acc0[NT][4], acc1[NT][4];
    #pragma unroll
    for (int nt = 0; nt < NT; nt++)
        #pragma unroll
        for (int k = 0; k < 4; k++) { acc0[nt][k] = 0.f; acc1[nt][k] = 0.f; }

    #pragma unroll 1
    for (int tap = 0; tap < 9; tap++) {
        const int dy = tap / 3, dx = tap % 3;
        const unsigned* a0b = tile + ((2 * w + dy) * TW + dx) * PW;
        const unsigned* a1b = a0b + TW * PW;
        const unsigned* wb  = sw1 + tap * COUT * PW;
        #pragma unroll
        for (int kb = 0; kb < KC; kb++) {
            const int ko = kb * 8 + 2 * t;
            uint2 ra0 = *(const uint2*)(a0b + g * PW + ko);
            uint2 rb0 = *(const uint2*)(a0b + (g + 8) * PW + ko);
            uint2 ra1 = *(const uint2*)(a1b + g * PW + ko);
            uint2 rb1 = *(const uint2*)(a1b + (g + 8) * PW + ko);
            #pragma unroll
            for (int nt = 0; nt < NT; nt++) {
                uint2 wv = *(const uint2*)(wb + (nt * 8 + g) * PW + ko);
                mma_bf16(acc0[nt], ra0.x, rb0.x, ra0.y, rb0.y, wv.x, wv.y);
                mma_bf16(acc1[nt], ra1.x, rb1.x, ra1.y, rb1.y, wv.x, wv.y);
            }
        }
    }

    // ---- chain: D fragments -> A fragments in registers -------------------
    #pragma unroll
    for (int rr = 0; rr < 2; rr++) {
        float (*acc)[4] = rr ? acc1 : acc0;

        unsigned afr[4][4];
        #pragma unroll
        for (int kb = 0; kb < 4; kb++) {
            int oc0 = kb * 16 + 2 * t;
            int oc1 = oc0 + 8;
            float b00 = sb1[oc0], b01 = sb1[oc0 + 1];
            float b10 = sb1[oc1], b11 = sb1[oc1 + 1];
            afr[kb][0] = bf2(fmaxf(acc[2*kb][0]+b00, 0.f), fmaxf(acc[2*kb][1]+b01, 0.f));
            afr[kb][1] = bf2(fmaxf(acc[2*kb][2]+b00, 0.f), fmaxf(acc[2*kb][3]+b01, 0.f));
            afr[kb][2] = bf2(fmaxf(acc[2*kb+1][0]+b10, 0.f), fmaxf(acc[2*kb+1][1]+b11, 0.f));
            afr[kb][3] = bf2(fmaxf(acc[2*kb+1][2]+b10, 0.f), fmaxf(acc[2*kb+1][3]+b11, 0.f));
        }
        float hacc[8][4];
        #pragma unroll
        for (int nt = 0; nt < 8; nt++)
            #pragma unroll
            for (int k = 0; k < 4; k++) hacc[nt][k] = 0.f;
        #pragma unroll
        for (int kb = 0; kb < 4; kb++) {
            const int ko = kb * 8 + 2 * t;
            #pragma unroll
            for (int nt = 0; nt < 8; nt++) {
                uint2 wv = *(const uint2*)(sw2 + (nt * 8 + g) * PWF + ko);
                mma_bf16(hacc[nt], afr[kb][0], afr[kb][1], afr[kb][2], afr[kb][3],
                         wv.x, wv.y);
            }
        }
        unsigned hfr[4][4];
        #pragma unroll
        for (int kb = 0; kb < 4; kb++) {
            int oc0 = kb * 16 + 2 * t;
            int oc1 = oc0 + 8;
            float b00 = sb2[oc0], b01 = sb2[oc0 + 1];
            float b10 = sb2[oc1], b11 = sb2[oc1 + 1];
            hfr[kb][0] = bf2(fmaxf(hacc[2*kb][0]+b00, 0.f), fmaxf(hacc[2*kb][1]+b01, 0.f));
            hfr[kb][1] = bf2(fmaxf(hacc[2*kb][2]+b00, 0.f), fmaxf(hacc[2*kb][3]+b01, 0.f));
            hfr[kb][2] = bf2(fmaxf(hacc[2*kb+1][0]+b10, 0.f), fmaxf(hacc[2*kb+1][1]+b11, 0.f));
            hfr[kb][3] = bf2(fmaxf(hacc[2*kb+1][2]+b10, 0.f), fmaxf(hacc[2*kb+1][3]+b11, 0.f));
        }
        float g3[2][4];
        #pragma unroll
        for (int nt = 0; nt < 2; nt++)
            #pragma unroll
            for (int k = 0; k < 4; k++) g3[nt][k] = 0.f;
        #pragma unroll
        for (int kb = 0; kb < 4; kb++) {
            const int ko = kb * 8 + 2 * t;
            #pragma unroll
            for (int nt = 0; nt < 2; nt++) {
                uint2 wv = *(const uint2*)(sw3 + (nt * 8 + g) * PWF + ko);
                mma_bf16(g3[nt], hfr[kb][0], hfr[kb][1], hfr[kb][2], hfr[kb][3],
                         wv.x, wv.y);
            }
        }
        float o0a = 0.f, o1a = 0.f, o0b = 0.f, o1b = 0.f;
        #pragma unroll
        for (int nt = 0; nt < 2; nt++) {
            #pragma unroll
            for (int p = 0; p < 2; p++) {
                int col = nt * 8 + 2 * t + p;
                float bi = sb3[col];
                float w0 = sw4f[col * 2], w1 = sw4f[col * 2 + 1];
                float va = fmaxf(g3[nt][p] + bi, 0.f);
                float vb = fmaxf(g3[nt][2 + p] + bi, 0.f);
                o0a = fmaf(va, w0, o0a); o1a = fmaf(va, w1, o1a);
                o0b = fmaf(vb, w0, o0b); o1b = fmaf(vb, w1, o1b);
            }
        }
        #pragma unroll
        for (int m = 1; m <= 2; m <<= 1) {
            o0a += __shfl_xor_sync(0xffffffffu, o0a, m);
            o1a += __shfl_xor_sync(0xffffffffu, o1a, m);
            o0b += __shfl_xor_sync(0xffffffffu, o0b, m);
            o1b += __shfl_xor_sync(0xffffffffu, o1b, m);
        }

        const int gy = by + 2 * w + rr;
        const int xA = bx + g, xB = xA + 8;
        size_t pixA = (size_t)((b * HH + gy) * WW + xA);
        size_t pixB = pixA + 8;
        float2 fA = ((const float2*)flow)[pixA];
        float2 fB = ((const float2*)flow)[pixB];
        float fcAx = fA.x + o0a + sb4[0], fcAy = fA.y + o1a + sb4[1];
        float fcBx = fB.x + o0b + sb4[0], fcBy = fB.y + o1b + sb4[1];
        if (t == 0) {
            ((float2*)flowch)[pixA] = make_float2(fcAx, fcAy);
            ((float2*)flowch)[pixB] = make_float2(fcBx, fcBy);
        }
        float qyA = (float)gy - fcAx, qxA = (float)xA - fcAy;
        float fyA = fminf(fmaxf(floorf(qyA), 0.f), (float)(HH - 2));
        float fxA = fminf(fmaxf(floorf(qxA), 0.f), (float)(WW - 2));
        float ayA = fminf(fmaxf(qyA - fyA, 0.f), 1.f);
        float axA = fminf(fmaxf(qxA - fxA, 0.f), 1.f);
        int baseA = ((b * HH + (int)fyA) * WW + (int)fxA) * 8;

        float qyB = (float)gy - fcBx, qxB = (float)xB - fcBy;
        float fyB = fminf(fmaxf(floorf(qyB), 0.f), (float)(HH - 2));
        float fxB = fminf(fmaxf(floorf(qxB), 0.f), (float)(WW - 2));
        float ayB = fminf(fmaxf(qyB - fyB, 0.f), 1.f);
        float axB = fminf(fmaxf(qxB - fxB, 0.f), 1.f);
        int baseB = ((b * HH + (int)fyB) * WW + (int)fxB) * 8;

        const float4* s4 = (const float4*)srcimg;
        float4* oA = (float4*)outWarped + pixA * 8;
        float4* oB = (float4*)outWarped + pixB * 8;
        #pragma unroll
        for (int cc = 0; cc < 2; cc++) {
            int c4 = t * 2 + cc;
            oA[c4] = bilin4(s4, baseA + c4, ayA, axA);
            oB[c4] = bilin4(s4, baseB + c4, ayB, axB);
        }
    }
}

// ---------------- 2x bilinear upsample — both dirs in one launch ----------
__global__ __launch_bounds__(256) void upsample_kernel(
    const float* __restrict__ src, float* __restrict__ out)
{
    int idx = blockIdx.x * blockDim.x + threadIdx.x;
    int x = idx & 511;
    int y = (idx >> 9) & 511;
    int b = idx >> 18;
    float sy = 0.5f * (float)y - 0.25f;
    float sx = 0.5f * (float)x - 0.25f;
    float y0f = floorf(sy), x0f = floorf(sx);
    float wy = sy - y0f,    wx = sx - x0f;
    int y0 = (int)y0f, x0 = (int)x0f;
    int ya = max(y0, 0), yb = min(y0 + 1, HH - 1);
    int xa = max(x0, 0), xb = min(x0 + 1, WW - 1);
    const float2* s = (const float2*)src;
    float2 v00 = s[(b * HH + ya) * WW + xa];
    float2 v01 = s[(b * HH + ya) * WW + xb];
    float2 v10 = s[(b * HH + yb) * WW + xa];
    float2 v11 = s[(b * HH + yb) * WW + xb];
    float2 r;
    r.x = (1.f - wy) * ((1.f - wx) * v00.x + wx * v01.x)
        +        wy  * ((1.f - wx) * v10.x + wx * v11.x);
    r.y = (1.f - wy) * ((1.f - wx) * v00.y + wx * v01.y)
        +        wy  * ((1.f - wx) * v10.y + wx * v11.y);
    ((float2*)out)[idx] = r;
}

// ---------------- launch ---------------------------------------------------
extern "C" void kernel_launch(void* const* d_in, const int* in_sizes, int n_in,
                              void* d_out, int out_size)
{
    (void)in_sizes; (void)n_in; (void)out_size;
    const float* input_1 = (const float*)d_in[0];
    const float* input_2 = (const float*)d_in[1];
    const float* flow12  = (const float*)d_in[2];
    const float* flow21  = (const float*)d_in[3];
    float* out = (float*)d_out;

    unsigned *c0w, *wpack, *imgw, *warpw;
    float *flowch, *bpack;
    cudaGetSymbolAddress((void**)&c0w,    g_c0_w);
    cudaGetSymbolAddress((void**)&flowch, g_flowch);
    cudaGetSymbolAddress((void**)&wpack,  g_wpack);
    cudaGetSymbolAddress((void**)&bpack,  g_bpack);
    cudaGetSymbolAddress((void**)&imgw,   g_img_w);
    cudaGetSymbolAddress((void**)&warpw,  g_warp_w);

    const int SM_CONV0 = (18 * 18 * PW0 + WPW_N0) * 4 + 32 * 4;
    const int SM_MEGA  = (18 * 18 * PW1 + WPW_N1 + WPW_F2 + WPW_F3) * 4 + 256 * 4;
    cudaFuncSetAttribute(conv0_tc_kernel,
                         cudaFuncAttributeMaxDynamicSharedMemorySize, SM_CONV0);
    cudaFuncSetAttribute(conv1_mega_kernel,
                         cudaFuncAttributeMaxDynamicSharedMemorySize, SM_MEGA);

    const float* w[2][5];
    const float* bw[2][5];
    for (int dir = 0; dir < 2; dir++)
        for (int i = 0; i < 5; i++) {
            w[dir][i]  = (const float*)d_in[4 + 4 * i + 2 * dir];
            bw[dir][i] = (const float*)d_in[4 + 4 * i + 2 * dir + 1];
        }

    {
        const int total = 2 * WPW_PER;
        prepack_kernel<<<(total + 255) / 256, 256>>>(
            w[0][0], w[0][1], w[0][2], w[0][3],
            w[1][0], w[1][1], w[1][2], w[1][3], wpack);
        biaspack_kernel<<<2, 256>>>(
            bw[0][0], bw[0][1], bw[0][2], bw[0][3], w[0][4], bw[0][4],
            bw[1][0], bw[1][1], bw[1][2], bw[1][3], w[1][4], bw[1][4], bpack);
        imgpack_kernel<<<2 * NPIXTOT * 16 / 256, 256>>>(input_1, input_2, imgw);
    }

    // bilinear warp (bf16 -> bf16), once per pixel, both dirs
    warpbf_kernel<<<2 * NPIXTOT * 2 / 256, 256>>>(imgw, flow12, flow21, warpw);

    dim3 grid(WW / 16, HH / 16, 2 * BB);

    conv0_tc_kernel<<<grid, 256, SM_CONV0>>>(imgw, warpw, wpack, bpack, c0w);
    conv1_mega_kernel<<<grid, 256, SM_MEGA>>>(
        c0w, input_1, input_2, flow12, flow21, wpack, bpack, out, flowch);
    upsample_kernel<<<2 * BB * 512 * 512 / 256, 256>>>(
        flowch, out + 2ull * NPIXTOT * 32);
}

// round 15
// speedup vs baseline: 1.0758x; 1.0758x over previous
#include <cuda_runtime.h>
#include <cuda_bf16.h>

#define BB 8
#define HH 256
#define WW 256
#define NPIXTOT (BB*HH*WW)

// ---------------- bf16 helpers ---------------------------------------------
__device__ __forceinline__ unsigned bf2(float lo, float hi) {
    __nv_bfloat162 h = __floats2bfloat162_rn(lo, hi);
    return *(unsigned*)&h;
}
__device__ __forceinline__ void mma_bf16(float* c,
    unsigned a0, unsigned a1, unsigned a2, unsigned a3,
    unsigned b0, unsigned b1)
{
    asm("mma.sync.aligned.m16n8k16.row.col.f32.bf16.bf16.f32 "
        "{%0,%1,%2,%3}, {%4,%5,%6,%7}, {%8,%9}, {%0,%1,%2,%3};"
        : "+f"(c[0]), "+f"(c[1]), "+f"(c[2]), "+f"(c[3])
        : "r"(a0), "r"(a1), "r"(a2), "r"(a3), "r"(b0), "r"(b1));
}

// QUAD-PAIR layout: within a 32-channel group (16 bf16-pair words), pair q
// (channels 2q,2q+1) lives at word  w(q) = (q&3)*4 + ((q>>2)&1) + ((q&8)?2:0).
// Thread t's uint4 at words 4t..4t+3 = pairs {t, t+4, 8+t, 12+t}
//   = kb0 fragment halves (x,y) and kb1 fragment halves (z,w).

// ---------------- scratch (device globals; no allocation allowed) ----------
__device__ unsigned g_c0_w[2ull * NPIXTOT * 16];   // conv0 out (quad-pair)
__device__ float    g_flowch[2ull * NPIXTOT * 2];

#define PWF 48
#define WPW_N0 (9*32*32)     /* conv0: rows tap*32+oc, pitch 32, XOR16 swizzle */
#define WPW_N1 (9*64*16)     /* conv1: rows tap*64+oc, pitch 16 */
#define WPW_F2 (64*PWF)
#define WPW_F3 (16*PWF)
#define WPW_PER (WPW_N0 + WPW_N1 + WPW_F2 + WPW_F3)
__device__ unsigned g_wpack[2 * WPW_PER];
#define BP_PER 256
__device__ float g_bpack[2 * BP_PER];

// ---------------- weight prepack -------------------------------------------
__global__ void prepack_kernel(
    const float* __restrict__ c0d0, const float* __restrict__ c1d0,
    const float* __restrict__ w2d0, const float* __restrict__ w3d0,
    const float* __restrict__ c0d1, const float* __restrict__ c1d1,
    const float* __restrict__ w2d1, const float* __restrict__ w3d1,
    unsigned* __restrict__ dst)
{
    int i = blockIdx.x * blockDim.x + threadIdx.x;
    if (i >= 2 * WPW_PER) return;
    int dir = (i >= WPW_PER);
    int j = i - dir * WPW_PER;
    float lo = 0.f, hi = 0.f;
    if (j < WPW_N0) {
        const float* w = dir ? c0d1 : c0d0;           // [tap][64][32]
        int row = j / 32, pw = j % 32;
        int lw = pw ^ ((row & 1) << 4);               // undo swizzle
        int grp = lw >> 4, w16 = lw & 15;
        int t = w16 >> 2, slot = w16 & 1, kbs = (w16 >> 1) & 1;
        int q = t + slot * 4 + kbs * 8;
        int ch = grp * 32 + 2 * q;
        int oc = row % 32, tap = row / 32;
        lo = w[(tap * 64 + ch) * 32 + oc];
        hi = w[(tap * 64 + ch + 1) * 32 + oc];
    } else if (j < WPW_N0 + WPW_N1) {
        j -= WPW_N0;
        const float* w = dir ? c1d1 : c1d0;           // [tap][32][64]
        int row = j / 16, w16 = j % 16;
        int t = w16 >> 2, slot = w16 & 1, kbs = (w16 >> 1) & 1;
        int ch = 2 * (t + slot * 4 + kbs * 8);
        int oc = row % 64, tap = row / 64;
        lo = w[(tap * 32 + ch) * 64 + oc];
        hi = w[(tap * 32 + ch + 1) * 64 + oc];
    } else if (j < WPW_N0 + WPW_N1 + WPW_F2) {
        j -= WPW_N0 + WPW_N1;
        const float* w = dir ? w2d1 : w2d0;           // [64][64]
        int oc = j / PWF, pw = j % PWF;
        if (pw < 32) {
            int grp = pw >> 4, w16 = pw & 15;
            int t = w16 >> 2, slot = w16 & 1, kbs = (w16 >> 1) & 1;
            int ch = grp * 32 + 2 * (t + slot * 4 + kbs * 8);
            lo = w[ch * 64 + oc];
            hi = w[(ch + 1) * 64 + oc];
        }
    } else {
        j -= WPW_N0 + WPW_N1 + WPW_F2;
        const float* w = dir ? w3d1 : w3d0;           // [64][16]
        int oc = j / PWF, pw = j % PWF;
        if (pw < 32) {
            int grp = pw >> 4, w16 = pw & 15;
            int t = w16 >> 2, slot = w16 & 1, kbs = (w16 >> 1) & 1;
            int ch = grp * 32 + 2 * (t + slot * 4 + kbs * 8);
            lo = w[ch * 16 + oc];
            hi = w[(ch + 1) * 16 + oc];
        }
    }
    dst[i] = bf2(lo, hi);
}

__global__ void biaspack_kernel(
    const float* __restrict__ b0d0, const float* __restrict__ b1d0,
    const float* __restrict__ b2d0, const float* __restrict__ b3d0,
    const float* __restrict__ w4d0, const float* __restrict__ b4d0,
    const float* __restrict__ b0d1, const float* __restrict__ b1d1,
    const float* __restrict__ b2d1, const float* __restrict__ b3d1,
    const float* __restrict__ w4d1, const float* __restrict__ b4d1,
    float* __restrict__ dst)
{
    int i = threadIdx.x;
    int dir = blockIdx.x;
    const float* srcs[6] = {
        dir ? b0d1 : b0d0, dir ? b1d1 : b1d0, dir ? b2d1 : b2d0,
        dir ? b3d1 : b3d0, dir ? w4d1 : w4d0, dir ? b4d1 : b4d0 };
    const int offs[7] = {0, 32, 96, 160, 176, 208, 210};
    float v = 0.f;
    #pragma unroll
    for (int s = 0; s < 6; s++)
        if (i >= offs[s] && i < offs[s + 1]) v = srcs[s][i - offs[s]];
    dst[dir * BP_PER + i] = v;
}

// ---------------- bilinear 4-channel gather (fp32 src) ----------------------
__device__ __forceinline__ float4 bilin4(const float4* s4, int base,
                                         float ay, float ax)
{
    float4 tl = s4[base];
    float4 tr = s4[base + 8];
    float4 bl = s4[base + WW * 8];
    float4 br = s4[base + WW * 8 + 8];
    float4 top, bot, r;
    top.x = tl.x + ax * (tr.x - tl.x); top.y = tl.y + ax * (tr.y - tl.y);
    top.z = tl.z + ax * (tr.z - tl.z); top.w = tl.w + ax * (tr.w - tl.w);
    bot.x = bl.x + ax * (br.x - bl.x); bot.y = bl.y + ax * (br.y - bl.y);
    bot.z = bl.z + ax * (br.z - bl.z); bot.w = bl.w + ax * (br.w - bl.w);
    r.x = top.x + ay * (bot.x - top.x); r.y = top.y + ay * (bot.y - top.y);
    r.z = top.z + ay * (bot.z - top.z); r.w = top.w + ay * (bot.w - top.w);
    return r;
}

// ---------------- conv0: 64->32, tile 16x16, fused warp+concat, quad-pair ---
__global__ __launch_bounds__(256, 2) void conv0_tc_kernel(
    const float* __restrict__ input_1, const float* __restrict__ input_2,
    const float* __restrict__ flow12, const float* __restrict__ flow21,
    const unsigned* __restrict__ wpackg, const float* __restrict__ bpackg,
    unsigned* __restrict__ c0wg)
{
    constexpr int COUT = 32;
    constexpr int TX = 16, TY = 16;
    constexpr int TW = TX + 2, TH = TY + 2;
    constexpr int PW = 32;                // words per pixel (64ch)
    constexpr int NT = COUT / 8;          // 4
    constexpr int TILE_W = TH * TW * PW;

    extern __shared__ unsigned smw[];
    unsigned* tile = smw;
    unsigned* sw   = smw + TILE_W;
    float*    sb   = (float*)(sw + WPW_N0);

    const int dir = blockIdx.z >> 3;
    const int b   = blockIdx.z & 7;
    const float* other  = dir ? input_1 : input_2;
    const float* srcimg = dir ? input_2 : input_1;
    const float* flow   = dir ? flow21 : flow12;
    const unsigned* wpack = wpackg + (size_t)dir * WPW_PER;
    const float* bias = bpackg + dir * BP_PER;
    unsigned* outw = c0wg + (size_t)dir * NPIXTOT * 16;

    const int bx = blockIdx.x * TX;
    const int by = blockIdx.y * TY;
    const int tid = threadIdx.x;

    {
        const uint4* s4 = (const uint4*)wpack;
        uint4* d4 = (uint4*)sw;
        #pragma unroll 4
        for (int i = tid; i < WPW_N0 / 4; i += 256) d4[i] = s4[i];
        if (tid < COUT) sb[tid] = bias[tid];
    }
    // staging: item = (pixel, kb 0..3 of 16 channels). kb<2: copy 'other';
    // kb>=2: bilinear gather from srcimg (fp32, same math as R11).
    for (int i = tid; i < TH * TW * 4; i += 256) {
        int kb = i & 3;
        int p  = i >> 2;
        int xx = p % TW;
        int yy = p / TW;
        int gx = bx + xx - 1;
        int gy = by + yy - 1;
        float4 v[4];
        v[0] = v[1] = v[2] = v[3] = make_float4(0.f, 0.f, 0.f, 0.f);
        if (gx >= 0 && gx < WW && gy >= 0 && gy < HH) {
            int pix = (b * HH + gy) * WW + gx;
            if (kb < 2) {
                const float4* s = (const float4*)other + (size_t)pix * 8 + kb * 4;
                v[0] = s[0]; v[1] = s[1]; v[2] = s[2]; v[3] = s[3];
            } else {
                float2 f = ((const float2*)flow)[pix];
                float qy = (float)gy - f.x;
                float qx = (float)gx - f.y;
                float fy = fminf(fmaxf(floorf(qy), 0.f), (float)(HH - 2));
                float fx = fminf(fmaxf(floorf(qx), 0.f), (float)(WW - 2));
                float ay = fminf(fmaxf(qy - fy, 0.f), 1.f);
                float ax = fminf(fmaxf(qx - fx, 0.f), 1.f);
                int iy = (int)fy, ix = (int)fx;
                const float4* s4 = (const float4*)srcimg;
                int base = ((b * HH + iy) * WW + ix) * 8 + (kb - 2) * 4;
                #pragma unroll
                for (int jj = 0; jj < 4; jj++)
                    v[jj] = bilin4(s4, base + jj, ay, ax);
            }
        }
        // channel group of this kb: grp = overall channel block /32
        // kb maps to channels kb*16..kb*16+15: grp = kb>>1, kbsel = kb&1.
        int grp = kb >> 1, kbs = kb & 1;
        unsigned base = p * PW + ((grp * 16) ^ ((p & 1) << 4)) + kbs * 2;
        // pairs j (0..7) within kb: channels 2j,2j+1 -> pv[j]
        // pair q_in_group = kbs*8 + j; word = (j&3)*4 + (j>>2) + kbs*2
        // write uint2 { pair j, pair j+4 } at word offset (j&3)*4 + kbs*2
        float2 pv[8];
        pv[0] = make_float2(v[0].x, v[0].y);
        pv[1] = make_float2(v[0].z, v[0].w);
        pv[2] = make_float2(v[1].x, v[1].y);
        pv[3] = make_float2(v[1].z, v[1].w);
        pv[4] = make_float2(v[2].x, v[2].y);
        pv[5] = make_float2(v[2].z, v[2].w);
        pv[6] = make_float2(v[3].x, v[3].y);
        pv[7] = make_float2(v[3].z, v[3].w);
        #pragma unroll
        for (int t2 = 0; t2 < 4; t2++) {
            uint2 wv = make_uint2(bf2(pv[t2].x, pv[t2].y),
                                  bf2(pv[t2 + 4].x, pv[t2 + 4].y));
            *(uint2*)(tile + base + t2 * 4) = wv;
        }
    }
    __syncthreads();

    const int lane = tid & 31;
    const int w    = tid >> 5;     // warp = rows 2w, 2w+1
    const int g = lane >> 2;
    const int t = lane & 3;

    float acc0[NT][4], acc1[NT][4];
    #pragma unroll
    for (int nt = 0; nt < NT; nt++)
        #pragma unroll
        for (int k = 0; k < 4; k++) { acc0[nt][k] = 0.f; acc1[nt][k] = 0.f; }

    const unsigned wswz = (g & 1) << 4;

    #pragma unroll 1
    for (int tap = 0; tap < 9; tap++) {
        const int dy = tap / 3, dx = tap % 3;
        const int p0 = (2 * w + dy) * TW + dx;
        // A loads: rows p0+g, p0+g+8 (rt0) and +TW (rt1); groups 0,1
        uint4 a0g[2], a0h[2], a1g[2], a1h[2];
        #pragma unroll
        for (int grp = 0; grp < 2; grp++) {
            int pa = p0 + g;
            a0g[grp] = *(const uint4*)(tile + pa * PW + ((grp * 16 + 4 * t) ^ ((pa & 1) << 4)));
            int pb = p0 + g + 8;
            a0h[grp] = *(const uint4*)(tile + pb * PW + ((grp * 16 + 4 * t) ^ ((pb & 1) << 4)));
            int pc = p0 + TW + g;
            a1g[grp] = *(const uint4*)(tile + pc * PW + ((grp * 16 + 4 * t) ^ ((pc & 1) << 4)));
            int pd = p0 + TW + g + 8;
            a1h[grp] = *(const uint4*)(tile + pd * PW + ((grp * 16 + 4 * t) ^ ((pd & 1) << 4)));
        }
        const unsigned* wb = sw + tap * COUT * PW;
        #pragma unroll
        for (int nt = 0; nt < NT; nt++) {
            const unsigned* wr = wb + (nt * 8 + g) * PW;
            #pragma unroll
            for (int grp = 0; grp < 2; grp++) {
                uint4 wv = *(const uint4*)(wr + ((grp * 16 + 4 * t) ^ wswz));
                mma_bf16(acc0[nt], a0g[grp].x, a0h[grp].x, a0g[grp].y, a0h[grp].y, wv.x, wv.y);
                mma_bf16(acc0[nt], a0g[grp].z, a0h[grp].z, a0g[grp].w, a0h[grp].w, wv.z, wv.w);
                mma_bf16(acc1[nt], a1g[grp].x, a1h[grp].x, a1g[grp].y, a1h[grp].y, wv.x, wv.y);
                mma_bf16(acc1[nt], a1g[grp].z, a1h[grp].z, a1g[grp].w, a1h[grp].w, wv.z, wv.w);
            }
        }
    }

    #pragma unroll
    for (int rr = 0; rr < 2; rr++) {
        const int gy = by + 2 * w + rr;
        float (*acc)[4] = rr ? acc1 : acc0;
        size_t pix0 = (size_t)((b * HH + gy) * WW + bx + g);
        unsigned* o0 = outw + pix0 * 16;
        unsigned* o1 = o0 + 8 * 16;
        #pragma unroll
        for (int nt = 0; nt < NT; nt++) {
            int oc = nt * 8 + 2 * t;
            int q = nt * 4 + t;
            int word = (q & 3) * 4 + ((q >> 2) & 1) + ((q & 8) ? 2 : 0);
            float bi0 = sb[oc], bi1 = sb[oc + 1];
            o0[word] = bf2(fmaxf(acc[nt][0] + bi0, 0.f), fmaxf(acc[nt][1] + bi1, 0.f));
            o1[word] = bf2(fmaxf(acc[nt][2] + bi0, 0.f), fmaxf(acc[nt][3] + bi1, 0.f));
        }
    }
}

// ---------------- MEGA: conv1 + 1x1 chain + flow add + final warp ----------
__global__ __launch_bounds__(256, 2) void conv1_mega_kernel(
    const unsigned* __restrict__ c0wg,
    const float* __restrict__ input_1, const float* __restrict__ input_2,
    const float* __restrict__ flow12, const float* __restrict__ flow21,
    const unsigned* __restrict__ wpackg, const float* __restrict__ bpackg,
    float* __restrict__ outAll, float* __restrict__ flowchg)
{
    constexpr int COUT = 64;
    constexpr int TX = 16, TY = 16;
    constexpr int TW = TX + 2, TH = TY + 2;
    constexpr int PW = 16;                // words per pixel (32ch)
    constexpr int NT = COUT / 8;          // 8
    constexpr int TILE_W = TH * TW * PW;

    extern __shared__ unsigned smw[];
    unsigned* tile = smw;
    unsigned* sw1  = smw + TILE_W;
    unsigned* sw2  = sw1 + WPW_N1;
    unsigned* sw3  = sw2 + WPW_F2;
    float*    sbf  = (float*)(sw3 + WPW_F3);

    const int dir = blockIdx.z >> 3;
    const int b   = blockIdx.z & 7;
    const float* srcimg = dir ? input_2 : input_1;
    const float* flow = dir ? flow21 : flow12;
    const unsigned* wbase = wpackg + (size_t)dir * WPW_PER;
    const unsigned* in = c0wg + (size_t)dir * NPIXTOT * 16;
    float* flowch = flowchg + (size_t)dir * NPIXTOT * 2;
    float* outWarped = outAll + (size_t)dir * NPIXTOT * 32;

    float* sb1  = sbf + 32;
    float* sb2  = sbf + 96;
    float* sb3  = sbf + 160;
    float* sw4f = sbf + 176;
    float* sb4  = sbf + 208;

    const int bx = blockIdx.x * TX;
    const int by = blockIdx.y * TY;
    const int tid = threadIdx.x;

    {
        const uint4* s1 = (const uint4*)(wbase + WPW_N0);
        uint4* d1 = (uint4*)sw1;
        #pragma unroll 4
        for (int i = tid; i < (WPW_N1 + WPW_F2 + WPW_F3) / 4; i += 256) d1[i] = s1[i];
        sbf[tid] = bpackg[dir * BP_PER + tid];
    }
    for (int i = tid; i < TH * TW * 4; i += 256) {
        int q = i & 3;
        int p = i >> 2;
        int xx = p % TW;
        int yy = p / TW;
        int gx = bx + xx - 1;
        int gy = by + yy - 1;
        uint4 v = make_uint4(0, 0, 0, 0);
        if (gx >= 0 && gx < WW && gy >= 0 && gy < HH) {
            size_t pix = (size_t)((b * HH + gy) * WW + gx);
            v = *(const uint4*)(in + pix * 16 + q * 4);
        }
        *(uint4*)(tile + p * PW + q * 4) = v;
    }
    __syncthreads();

    const int lane = tid & 31;
    const int w    = tid >> 5;
    const int g = lane >> 2;
    const int t = lane & 3;

    float acc0[NT][4], acc1[NT][4];
    #pragma unroll
    for (int nt = 0; nt < NT; nt++)
        #pragma unroll
        for (int k = 0; k < 4; k++) { acc0[nt][k] = 0.f; acc1[nt][k] = 0.f; }

    #pragma unroll 1
    for (int tap = 0; tap < 9; tap++) {
        const int dy = tap / 3, dx = tap % 3;
        const int p0 = (2 * w + dy) * TW + dx;
        uint4 a0g = *(const uint4*)(tile + (p0 + g) * PW + 4 * t);
        uint4 a0h = *(const uint4*)(tile + (p0 + g + 8) * PW + 4 * t);
        uint4 a1g = *(const uint4*)(tile + (p0 + TW + g) * PW + 4 * t);
        uint4 a1h = *(const uint4*)(tile + (p0 + TW + g + 8) * PW + 4 * t);
        const unsigned* wb = sw1 + tap * COUT * PW;
        #pragma unroll
        for (int nt = 0; nt < NT; nt++) {
            uint4 wv = *(const uint4*)(wb + (nt * 8 + g) * PW + 4 * t);
            mma_bf16(acc0[nt], a0g.x, a0h.x, a0g.y, a0h.y, wv.x, wv.y);
            mma_bf16(acc0[nt], a0g.z, a0h.z, a0g.w, a0h.w, wv.z, wv.w);
            mma_bf16(acc1[nt], a1g.x, a1h.x, a1g.y, a1h.y, wv.x, wv.y);
            mma_bf16(acc1[nt], a1g.z, a1h.z, a1g.w, a1h.w, wv.z, wv.w);
        }
    }

    // ---- chain: D fragments -> A fragments in registers -------------------
    #pragma unroll
    for (int rr = 0; rr < 2; rr++) {
        float (*acc)[4] = rr ? acc1 : acc0;

        unsigned afr[4][4];
        #pragma unroll
        for (int kb = 0; kb < 4; kb++) {
            int oc0 = kb * 16 + 2 * t;
            int oc1 = oc0 + 8;
            float b00 = sb1[oc0], b01 = sb1[oc0 + 1];
            float b10 = sb1[oc1], b11 = sb1[oc1 + 1];
            afr[kb][0] = bf2(fmaxf(acc[2*kb][0]+b00, 0.f), fmaxf(acc[2*kb][1]+b01, 0.f));
            afr[kb][1] = bf2(fmaxf(acc[2*kb][2]+b00, 0.f), fmaxf(acc[2*kb][3]+b01, 0.f));
            afr[kb][2] = bf2(fmaxf(acc[2*kb+1][0]+b10, 0.f), fmaxf(acc[2*kb+1][1]+b11, 0.f));
            afr[kb][3] = bf2(fmaxf(acc[2*kb+1][2]+b10, 0.f), fmaxf(acc[2*kb+1][3]+b11, 0.f));
        }
        float hacc[8][4];
        #pragma unroll
        for (int nt = 0; nt < 8; nt++)
            #pragma unroll
            for (int k = 0; k < 4; k++) hacc[nt][k] = 0.f;
        #pragma unroll
        for (int grp = 0; grp < 2; grp++) {
            #pragma unroll
            for (int nt = 0; nt < 8; nt++) {
                uint4 wv = *(const uint4*)(sw2 + (nt * 8 + g) * PWF + grp * 16 + 4 * t);
                mma_bf16(hacc[nt], afr[2*grp][0], afr[2*grp][1], afr[2*grp][2], afr[2*grp][3],
                         wv.x, wv.y);
                mma_bf16(hacc[nt], afr[2*grp+1][0], afr[2*grp+1][1], afr[2*grp+1][2], afr[2*grp+1][3],
                         wv.z, wv.w);
            }
        }
        unsigned hfr[4][4];
        #pragma unroll
        for (int kb = 0; kb < 4; kb++) {
            int oc0 = kb * 16 + 2 * t;
            int oc1 = oc0 + 8;
            float b00 = sb2[oc0], b01 = sb2[oc0 + 1];
            float b10 = sb2[oc1], b11 = sb2[oc1 + 1];
            hfr[kb][0] = bf2(fmaxf(hacc[2*kb][0]+b00, 0.f), fmaxf(hacc[2*kb][1]+b01, 0.f));
            hfr[kb][1] = bf2(fmaxf(hacc[2*kb][2]+b00, 0.f), fmaxf(hacc[2*kb][3]+b01, 0.f));
            hfr[kb][2] = bf2(fmaxf(hacc[2*kb+1][0]+b10, 0.f), fmaxf(hacc[2*kb+1][1]+b11, 0.f));
            hfr[kb][3] = bf2(fmaxf(hacc[2*kb+1][2]+b10, 0.f), fmaxf(hacc[2*kb+1][3]+b11, 0.f));
        }
        float g3[2][4];
        #pragma unroll
        for (int nt = 0; nt < 2; nt++)
            #pragma unroll
            for (int k = 0; k < 4; k++) g3[nt][k] = 0.f;
        #pragma unroll
        for (int grp = 0; grp < 2; grp++) {
            #pragma unroll
            for (int nt = 0; nt < 2; nt++) {
                uint4 wv = *(const uint4*)(sw3 + (nt * 8 + g) * PWF + grp * 16 + 4 * t);
                mma_bf16(g3[nt], hfr[2*grp][0], hfr[2*grp][1], hfr[2*grp][2], hfr[2*grp][3],
                         wv.x, wv.y);
                mma_bf16(g3[nt], hfr[2*grp+1][0], hfr[2*grp+1][1], hfr[2*grp+1][2], hfr[2*grp+1][3],
                         wv.z, wv.w);
            }
        }
        float o0a = 0.f, o1a = 0.f, o0b = 0.f, o1b = 0.f;
        #pragma unroll
        for (int nt = 0; nt < 2; nt++) {
            #pragma unroll
            for (int p = 0; p < 2; p++) {
                int col = nt * 8 + 2 * t + p;
                float bi = sb3[col];
                float w0 = sw4f[col * 2], w1 = sw4f[col * 2 + 1];
                float va = fmaxf(g3[nt][p] + bi, 0.f);
                float vb = fmaxf(g3[nt][2 + p] + bi, 0.f);
                o0a = fmaf(va, w0, o0a); o1a = fmaf(va, w1, o1a);
                o0b = fmaf(vb, w0, o0b); o1b = fmaf(vb, w1, o1b);
            }
        }
        #pragma unroll
        for (int m = 1; m <= 2; m <<= 1) {
            o0a += __shfl_xor_sync(0xffffffffu, o0a, m);
            o1a += __shfl_xor_sync(0xffffffffu, o1a, m);
            o0b += __shfl_xor_sync(0xffffffffu, o0b, m);
            o1b += __shfl_xor_sync(0xffffffffu, o1b, m);
        }

        const int gy = by + 2 * w + rr;
        const int xA = bx + g, xB = xA + 8;
        size_t pixA = (size_t)((b * HH + gy) * WW + xA);
        size_t pixB = pixA + 8;
        float2 fA = ((const float2*)flow)[pixA];
        float2 fB = ((const float2*)flow)[pixB];
        float fcAx = fA.x + o0a + sb4[0], fcAy = fA.y + o1a + sb4[1];
        float fcBx = fB.x + o0b + sb4[0], fcBy = fB.y + o1b + sb4[1];
        if (t == 0) {
            ((float2*)flowch)[pixA] = make_float2(fcAx, fcAy);
            ((float2*)flowch)[pixB] = make_float2(fcBx, fcBy);
        }
        float qyA = (float)gy - fcAx, qxA = (float)xA - fcAy;
        float fyA = fminf(fmaxf(floorf(qyA), 0.f), (float)(HH - 2));
        float fxA = fminf(fmaxf(floorf(qxA), 0.f), (float)(WW - 2));
        float ayA = fminf(fmaxf(qyA - fyA, 0.f), 1.f);
        float axA = fminf(fmaxf(qxA - fxA, 0.f), 1.f);
        int baseA = ((b * HH + (int)fyA) * WW + (int)fxA) * 8;

        float qyB = (float)gy - fcBx, qxB = (float)xB - fcBy;
        float fyB = fminf(fmaxf(floorf(qyB), 0.f), (float)(HH - 2));
        float fxB = fminf(fmaxf(floorf(qxB), 0.f), (float)(WW - 2));
        float ayB = fminf(fmaxf(qyB - fyB, 0.f), 1.f);
        float axB = fminf(fmaxf(qxB - fxB, 0.f), 1.f);
        int baseB = ((b * HH + (int)fyB) * WW + (int)fxB) * 8;

        const float4* s4 = (const float4*)srcimg;
        float4* oA = (float4*)outWarped + pixA * 8;
        float4* oB = (float4*)outWarped + pixB * 8;
        #pragma unroll
        for (int cc = 0; cc < 2; cc++) {
            int c4 = t * 2 + cc;
            oA[c4] = bilin4(s4, baseA + c4, ayA, axA);
            oB[c4] = bilin4(s4, baseB + c4, ayB, axB);
        }
    }
}

// ---------------- 2x bilinear upsample — both dirs in one launch ----------
__global__ __launch_bounds__(256) void upsample_kernel(
    const float* __restrict__ src, float* __restrict__ out)
{
    int idx = blockIdx.x * blockDim.x + threadIdx.x;
    int x = idx & 511;
    int y = (idx >> 9) & 511;
    int b = idx >> 18;
    float sy = 0.5f * (float)y - 0.25f;
    float sx = 0.5f * (float)x - 0.25f;
    float y0f = floorf(sy), x0f = floorf(sx);
    float wy = sy - y0f,    wx = sx - x0f;
    int y0 = (int)y0f, x0 = (int)x0f;
    int ya = max(y0, 0), yb = min(y0 + 1, HH - 1);
    int xa = max(x0, 0), xb = min(x0 + 1, WW - 1);
    const float2* s = (const float2*)src;
    float2 v00 = s[(b * HH + ya) * WW + xa];
    float2 v01 = s[(b * HH + ya) * WW + xb];
    float2 v10 = s[(b * HH + yb) * WW + xa];
    float2 v11 = s[(b * HH + yb) * WW + xb];
    float2 r;
    r.x = (1.f - wy) * ((1.f - wx) * v00.x + wx * v01.x)
        +        wy  * ((1.f - wx) * v10.x + wx * v11.x);
    r.y = (1.f - wy) * ((1.f - wx) * v00.y + wx * v01.y)
        +        wy  * ((1.f - wx) * v10.y + wx * v11.y);
    ((float2*)out)[idx] = r;
}

// ---------------- launch ---------------------------------------------------
extern "C" void kernel_launch(void* const* d_in, const int* in_sizes, int n_in,
                              void* d_out, int out_size)
{
    (void)in_sizes; (void)n_in; (void)out_size;
    const float* input_1 = (const float*)d_in[0];
    const float* input_2 = (const float*)d_in[1];
    const float* flow12  = (const float*)d_in[2];
    const float* flow21  = (const float*)d_in[3];
    float* out = (float*)d_out;

    unsigned *c0w, *wpack;
    float *flowch, *bpack;
    cudaGetSymbolAddress((void**)&c0w,    g_c0_w);
    cudaGetSymbolAddress((void**)&flowch, g_flowch);
    cudaGetSymbolAddress((void**)&wpack,  g_wpack);
    cudaGetSymbolAddress((void**)&bpack,  g_bpack);

    const int SM_CONV0 = (18 * 18 * 32 + WPW_N0) * 4 + 32 * 4;
    const int SM_MEGA  = (18 * 18 * 16 + WPW_N1 + WPW_F2 + WPW_F3) * 4 + 256 * 4;
    cudaFuncSetAttribute(conv0_tc_kernel,
                         cudaFuncAttributeMaxDynamicSharedMemorySize, SM_CONV0);
    cudaFuncSetAttribute(conv1_mega_kernel,
                         cudaFuncAttributeMaxDynamicSharedMemorySize, SM_MEGA);

    const float* w[2][5];
    const float* bw[2][5];
    for (int dir = 0; dir < 2; dir++)
        for (int i = 0; i < 5; i++) {
            w[dir][i]  = (const float*)d_in[4 + 4 * i + 2 * dir];
            bw[dir][i] = (const float*)d_in[4 + 4 * i + 2 * dir + 1];
        }

    {
        const int total = 2 * WPW_PER;
        prepack_kernel<<<(total + 255) / 256, 256>>>(
            w[0][0], w[0][1], w[0][2], w[0][3],
            w[1][0], w[1][1], w[1][2], w[1][3], wpack);
        biaspack_kernel<<<2, 256>>>(
            bw[0][0], bw[0][1], bw[0][2], bw[0][3], w[0][4], bw[0][4],
            bw[1][0], bw[1][1], bw[1][2], bw[1][3], w[1][4], bw[1][4], bpack);
    }

    dim3 grid(WW / 16, HH / 16, 2 * BB);

    conv0_tc_kernel<<<grid, 256, SM_CONV0>>>(
        input_1, input_2, flow12, flow21, wpack, bpack, c0w);
    conv1_mega_kernel<<<grid, 256, SM_MEGA>>>(
        c0w, input_1, input_2, flow12, flow21, wpack, bpack, out, flowch);
    upsample_kernel<<<2 * BB * 512 * 512 / 256, 256>>>(
        flowch, out + 2ull * NPIXTOT * 32);
}

// round 16
// speedup vs baseline: 1.0955x; 1.0183x over previous
#include <cuda_runtime.h>
#include <cuda_bf16.h>

#define BB 8
#define HH 256
#define WW 256
#define NPIXTOT (BB*HH*WW)

// ---------------- bf16 helpers ---------------------------------------------
__device__ __forceinline__ unsigned bf2(float lo, float hi) {
    __nv_bfloat162 h = __floats2bfloat162_rn(lo, hi);
    return *(unsigned*)&h;
}
__device__ __forceinline__ void mma_bf16(float* c,
    unsigned a0, unsigned a1, unsigned a2, unsigned a3,
    unsigned b0, unsigned b1)
{
    asm("mma.sync.aligned.m16n8k16.row.col.f32.bf16.bf16.f32 "
        "{%0,%1,%2,%3}, {%4,%5,%6,%7}, {%8,%9}, {%0,%1,%2,%3};"
        : "+f"(c[0]), "+f"(c[1]), "+f"(c[2]), "+f"(c[3])
        : "r"(a0), "r"(a1), "r"(a2), "r"(a3), "r"(b0), "r"(b1));
}

// QUAD-PAIR layout: within a 32-channel group (16 bf16-pair words), pair q
// (channels 2q,2q+1) lives at word  w(q) = (q&3)*4 + ((q>>2)&1) + ((q&8)?2:0).
// Thread t's uint4 at words 4t..4t+3 = pairs {t, t+4, 8+t, 12+t}.

// ---------------- scratch (device globals; no allocation allowed) ----------
__device__ unsigned g_c0_w[2ull * NPIXTOT * 16];   // conv0 out (quad-pair)
__device__ float    g_flowch[2ull * NPIXTOT * 2];

#define PWF 48
#define WPW_N0 (9*32*32)     /* conv0: rows tap*32+oc, pitch 32, XOR16 swizzle */
#define WPW_N1 (9*64*16)     /* conv1: rows tap*64+oc, pitch 16 */
#define WPW_F2 (64*PWF)
#define WPW_F3 (16*PWF)
#define WPW_PER (WPW_N0 + WPW_N1 + WPW_F2 + WPW_F3)
__device__ unsigned g_wpack[2 * WPW_PER];
#define BP_PER 256
__device__ float g_bpack[2 * BP_PER];

// ---------------- weight prepack -------------------------------------------
__global__ void prepack_kernel(
    const float* __restrict__ c0d0, const float* __restrict__ c1d0,
    const float* __restrict__ w2d0, const float* __restrict__ w3d0,
    const float* __restrict__ c0d1, const float* __restrict__ c1d1,
    const float* __restrict__ w2d1, const float* __restrict__ w3d1,
    unsigned* __restrict__ dst)
{
    int i = blockIdx.x * blockDim.x + threadIdx.x;
    if (i >= 2 * WPW_PER) return;
    int dir = (i >= WPW_PER);
    int j = i - dir * WPW_PER;
    float lo = 0.f, hi = 0.f;
    if (j < WPW_N0) {
        const float* w = dir ? c0d1 : c0d0;           // [tap][64][32]
        int row = j / 32, pw = j % 32;
        int lw = pw ^ ((row & 1) << 4);
        int grp = lw >> 4, w16 = lw & 15;
        int t = w16 >> 2, slot = w16 & 1, kbs = (w16 >> 1) & 1;
        int q = t + slot * 4 + kbs * 8;
        int ch = grp * 32 + 2 * q;
        int oc = row % 32, tap = row / 32;
        lo = w[(tap * 64 + ch) * 32 + oc];
        hi = w[(tap * 64 + ch + 1) * 32 + oc];
    } else if (j < WPW_N0 + WPW_N1) {
        j -= WPW_N0;
        const float* w = dir ? c1d1 : c1d0;           // [tap][32][64]
        int row = j / 16, w16 = j % 16;
        int t = w16 >> 2, slot = w16 & 1, kbs = (w16 >> 1) & 1;
        int ch = 2 * (t + slot * 4 + kbs * 8);
        int oc = row % 64, tap = row / 64;
        lo = w[(tap * 32 + ch) * 64 + oc];
        hi = w[(tap * 32 + ch + 1) * 64 + oc];
    } else if (j < WPW_N0 + WPW_N1 + WPW_F2) {
        j -= WPW_N0 + WPW_N1;
        const float* w = dir ? w2d1 : w2d0;           // [64][64]
        int oc = j / PWF, pw = j % PWF;
        if (pw < 32) {
            int grp = pw >> 4, w16 = pw & 15;
            int t = w16 >> 2, slot = w16 & 1, kbs = (w16 >> 1) & 1;
            int ch = grp * 32 + 2 * (t + slot * 4 + kbs * 8);
            lo = w[ch * 64 + oc];
            hi = w[(ch + 1) * 64 + oc];
        }
    } else {
        j -= WPW_N0 + WPW_N1 + WPW_F2;
        const float* w = dir ? w3d1 : w3d0;           // [64][16]
        int oc = j / PWF, pw = j % PWF;
        if (pw < 32) {
            int grp = pw >> 4, w16 = pw & 15;
            int t = w16 >> 2, slot = w16 & 1, kbs = (w16 >> 1) & 1;
            int ch = grp * 32 + 2 * (t + slot * 4 + kbs * 8);
            lo = w[ch * 16 + oc];
            hi = w[(ch + 1) * 16 + oc];
        }
    }
    dst[i] = bf2(lo, hi);
}

__global__ void biaspack_kernel(
    const float* __restrict__ b0d0, const float* __restrict__ b1d0,
    const float* __restrict__ b2d0, const float* __restrict__ b3d0,
    const float* __restrict__ w4d0, const float* __restrict__ b4d0,
    const float* __restrict__ b0d1, const float* __restrict__ b1d1,
    const float* __restrict__ b2d1, const float* __restrict__ b3d1,
    const float* __restrict__ w4d1, const float* __restrict__ b4d1,
    float* __restrict__ dst)
{
    int i = threadIdx.x;
    int dir = blockIdx.x;
    const float* srcs[6] = {
        dir ? b0d1 : b0d0, dir ? b1d1 : b1d0, dir ? b2d1 : b2d0,
        dir ? b3d1 : b3d0, dir ? w4d1 : w4d0, dir ? b4d1 : b4d0 };
    const int offs[7] = {0, 32, 96, 160, 176, 208, 210};
    float v = 0.f;
    #pragma unroll
    for (int s = 0; s < 6; s++)
        if (i >= offs[s] && i < offs[s + 1]) v = srcs[s][i - offs[s]];
    dst[dir * BP_PER + i] = v;
}

// ---------------- bilinear 4-channel gather (fp32 src) ----------------------
__device__ __forceinline__ float4 bilin4(const float4* s4, int base,
                                         float ay, float ax)
{
    float4 tl = s4[base];
    float4 tr = s4[base + 8];
    float4 bl = s4[base + WW * 8];
    float4 br = s4[base + WW * 8 + 8];
    float4 top, bot, r;
    top.x = tl.x + ax * (tr.x - tl.x); top.y = tl.y + ax * (tr.y - tl.y);
    top.z = tl.z + ax * (tr.z - tl.z); top.w = tl.w + ax * (tr.w - tl.w);
    bot.x = bl.x + ax * (br.x - bl.x); bot.y = bl.y + ax * (br.y - bl.y);
    bot.z = bl.z + ax * (br.z - bl.z); bot.w = bl.w + ax * (br.w - bl.w);
    r.x = top.x + ay * (bot.x - top.x); r.y = top.y + ay * (bot.y - top.y);
    r.z = top.z + ay * (bot.z - top.z); r.w = top.w + ay * (bot.w - top.w);
    return r;
}

// ---------------- conv0: 64->32, tile 16x16, fused warp+concat, quad-pair ---
__global__ __launch_bounds__(256, 2) void conv0_tc_kernel(
    const float* __restrict__ input_1, const float* __restrict__ input_2,
    const float* __restrict__ flow12, const float* __restrict__ flow21,
    const unsigned* __restrict__ wpackg, const float* __restrict__ bpackg,
    unsigned* __restrict__ c0wg)
{
    constexpr int COUT = 32;
    constexpr int TX = 16, TY = 16;
    constexpr int TW = TX + 2, TH = TY + 2;
    constexpr int PW = 32;
    constexpr int NT = COUT / 8;          // 4
    constexpr int TILE_W = TH * TW * PW;

    extern __shared__ unsigned smw[];
    unsigned* tile = smw;
    unsigned* sw   = smw + TILE_W;
    float*    sb   = (float*)(sw + WPW_N0);

    const int dir = blockIdx.z >> 3;
    const int b   = blockIdx.z & 7;
    const float* other  = dir ? input_1 : input_2;
    const float* srcimg = dir ? input_2 : input_1;
    const float* flow   = dir ? flow21 : flow12;
    const unsigned* wpack = wpackg + (size_t)dir * WPW_PER;
    const float* bias = bpackg + dir * BP_PER;
    unsigned* outw = c0wg + (size_t)dir * NPIXTOT * 16;

    const int bx = blockIdx.x * TX;
    const int by = blockIdx.y * TY;
    const int tid = threadIdx.x;

    {
        const uint4* s4 = (const uint4*)wpack;
        uint4* d4 = (uint4*)sw;
        #pragma unroll 4
        for (int i = tid; i < WPW_N0 / 4; i += 256) d4[i] = s4[i];
        if (tid < COUT) sb[tid] = bias[tid];
    }
    for (int i = tid; i < TH * TW * 4; i += 256) {
        int kb = i & 3;
        int p  = i >> 2;
        int xx = p % TW;
        int yy = p / TW;
        int gx = bx + xx - 1;
        int gy = by + yy - 1;
        float4 v[4];
        v[0] = v[1] = v[2] = v[3] = make_float4(0.f, 0.f, 0.f, 0.f);
        if (gx >= 0 && gx < WW && gy >= 0 && gy < HH) {
            int pix = (b * HH + gy) * WW + gx;
            if (kb < 2) {
                const float4* s = (const float4*)other + (size_t)pix * 8 + kb * 4;
                v[0] = s[0]; v[1] = s[1]; v[2] = s[2]; v[3] = s[3];
            } else {
                float2 f = ((const float2*)flow)[pix];
                float qy = (float)gy - f.x;
                float qx = (float)gx - f.y;
                float fy = fminf(fmaxf(floorf(qy), 0.f), (float)(HH - 2));
                float fx = fminf(fmaxf(floorf(qx), 0.f), (float)(WW - 2));
                float ay = fminf(fmaxf(qy - fy, 0.f), 1.f);
                float ax = fminf(fmaxf(qx - fx, 0.f), 1.f);
                int iy = (int)fy, ix = (int)fx;
                const float4* s4 = (const float4*)srcimg;
                int base = ((b * HH + iy) * WW + ix) * 8 + (kb - 2) * 4;
                #pragma unroll
                for (int jj = 0; jj < 4; jj++)
                    v[jj] = bilin4(s4, base + jj, ay, ax);
            }
        }
        int grp = kb >> 1, kbs = kb & 1;
        unsigned base = p * PW + ((grp * 16) ^ ((p & 1) << 4)) + kbs * 2;
        float2 pv[8];
        pv[0] = make_float2(v[0].x, v[0].y);
        pv[1] = make_float2(v[0].z, v[0].w);
        pv[2] = make_float2(v[1].x, v[1].y);
        pv[3] = make_float2(v[1].z, v[1].w);
        pv[4] = make_float2(v[2].x, v[2].y);
        pv[5] = make_float2(v[2].z, v[2].w);
        pv[6] = make_float2(v[3].x, v[3].y);
        pv[7] = make_float2(v[3].z, v[3].w);
        #pragma unroll
        for (int t2 = 0; t2 < 4; t2++) {
            uint2 wv = make_uint2(bf2(pv[t2].x, pv[t2].y),
                                  bf2(pv[t2 + 4].x, pv[t2 + 4].y));
            *(uint2*)(tile + base + t2 * 4) = wv;
        }
    }
    __syncthreads();

    const int lane = tid & 31;
    const int w    = tid >> 5;
    const int g = lane >> 2;
    const int t = lane & 3;

    float acc0[NT][4], acc1[NT][4];
    #pragma unroll
    for (int nt = 0; nt < NT; nt++)
        #pragma unroll
        for (int k = 0; k < 4; k++) { acc0[nt][k] = 0.f; acc1[nt][k] = 0.f; }

    const unsigned wswz = (g & 1) << 4;

    // FULLY UNROLLED tap loop: all tile/weight offsets constant-fold.
    #pragma unroll
    for (int tap = 0; tap < 9; tap++) {
        const int dy = tap / 3, dx = tap % 3;
        const int p0 = (2 * w + dy) * TW + dx;
        uint4 a0g[2], a0h[2], a1g[2], a1h[2];
        #pragma unroll
        for (int grp = 0; grp < 2; grp++) {
            int pa = p0 + g;
            a0g[grp] = *(const uint4*)(tile + pa * PW + ((grp * 16 + 4 * t) ^ ((pa & 1) << 4)));
            int pb = p0 + g + 8;
            a0h[grp] = *(const uint4*)(tile + pb * PW + ((grp * 16 + 4 * t) ^ ((pb & 1) << 4)));
            int pc = p0 + TW + g;
            a1g[grp] = *(const uint4*)(tile + pc * PW + ((grp * 16 + 4 * t) ^ ((pc & 1) << 4)));
            int pd = p0 + TW + g + 8;
            a1h[grp] = *(const uint4*)(tile + pd * PW + ((grp * 16 + 4 * t) ^ ((pd & 1) << 4)));
        }
        const unsigned* wb = sw + tap * COUT * PW;
        #pragma unroll
        for (int nt = 0; nt < NT; nt++) {
            const unsigned* wr = wb + (nt * 8 + g) * PW;
            #pragma unroll
            for (int grp = 0; grp < 2; grp++) {
                uint4 wv = *(const uint4*)(wr + ((grp * 16 + 4 * t) ^ wswz));
                mma_bf16(acc0[nt], a0g[grp].x, a0h[grp].x, a0g[grp].y, a0h[grp].y, wv.x, wv.y);
                mma_bf16(acc0[nt], a0g[grp].z, a0h[grp].z, a0g[grp].w, a0h[grp].w, wv.z, wv.w);
                mma_bf16(acc1[nt], a1g[grp].x, a1h[grp].x, a1g[grp].y, a1h[grp].y, wv.x, wv.y);
                mma_bf16(acc1[nt], a1g[grp].z, a1h[grp].z, a1g[grp].w, a1h[grp].w, wv.z, wv.w);
            }
        }
    }

    #pragma unroll
    for (int rr = 0; rr < 2; rr++) {
        const int gy = by + 2 * w + rr;
        float (*acc)[4] = rr ? acc1 : acc0;
        size_t pix0 = (size_t)((b * HH + gy) * WW + bx + g);
        unsigned* o0 = outw + pix0 * 16;
        unsigned* o1 = o0 + 8 * 16;
        #pragma unroll
        for (int nt = 0; nt < NT; nt++) {
            int oc = nt * 8 + 2 * t;
            int q = nt * 4 + t;
            int word = (q & 3) * 4 + ((q >> 2) & 1) + ((q & 8) ? 2 : 0);
            float bi0 = sb[oc], bi1 = sb[oc + 1];
            o0[word] = bf2(fmaxf(acc[nt][0] + bi0, 0.f), fmaxf(acc[nt][1] + bi1, 0.f));
            o1[word] = bf2(fmaxf(acc[nt][2] + bi0, 0.f), fmaxf(acc[nt][3] + bi1, 0.f));
        }
    }
}

// ---------------- MEGA: conv1 + 1x1 chain + flow add + final warp ----------
__global__ __launch_bounds__(256, 2) void conv1_mega_kernel(
    const unsigned* __restrict__ c0wg,
    const float* __restrict__ input_1, const float* __restrict__ input_2,
    const float* __restrict__ flow12, const float* __restrict__ flow21,
    const unsigned* __restrict__ wpackg, const float* __restrict__ bpackg,
    float* __restrict__ outAll, float* __restrict__ flowchg)
{
    constexpr int COUT = 64;
    constexpr int TX = 16, TY = 16;
    constexpr int TW = TX + 2, TH = TY + 2;
    constexpr int PW = 16;
    constexpr int NT = COUT / 8;          // 8
    constexpr int TILE_W = TH * TW * PW;

    extern __shared__ unsigned smw[];
    unsigned* tile = smw;
    unsigned* sw1  = smw + TILE_W;
    unsigned* sw2  = sw1 + WPW_N1;
    unsigned* sw3  = sw2 + WPW_F2;
    float*    sbf  = (float*)(sw3 + WPW_F3);

    const int dir = blockIdx.z >> 3;
    const int b   = blockIdx.z & 7;
    const float* srcimg = dir ? input_2 : input_1;
    const float* flow = dir ? flow21 : flow12;
    const unsigned* wbase = wpackg + (size_t)dir * WPW_PER;
    const unsigned* in = c0wg + (size_t)dir * NPIXTOT * 16;
    float* flowch = flowchg + (size_t)dir * NPIXTOT * 2;
    float* outWarped = outAll + (size_t)dir * NPIXTOT * 32;

    float* sb1  = sbf + 32;
    float* sb2  = sbf + 96;
    float* sb3  = sbf + 160;
    float* sw4f = sbf + 176;
    float* sb4  = sbf + 208;

    const int bx = blockIdx.x * TX;
    const int by = blockIdx.y * TY;
    const int tid = threadIdx.x;

    {
        const uint4* s1 = (const uint4*)(wbase + WPW_N0);
        uint4* d1 = (uint4*)sw1;
        #pragma unroll 4
        for (int i = tid; i < (WPW_N1 + WPW_F2 + WPW_F3) / 4; i += 256) d1[i] = s1[i];
        sbf[tid] = bpackg[dir * BP_PER + tid];
    }
    for (int i = tid; i < TH * TW * 4; i += 256) {
        int q = i & 3;
        int p = i >> 2;
        int xx = p % TW;
        int yy = p / TW;
        int gx = bx + xx - 1;
        int gy = by + yy - 1;
        uint4 v = make_uint4(0, 0, 0, 0);
        if (gx >= 0 && gx < WW && gy >= 0 && gy < HH) {
            size_t pix = (size_t)((b * HH + gy) * WW + gx);
            v = *(const uint4*)(in + pix * 16 + q * 4);
        }
        *(uint4*)(tile + p * PW + q * 4) = v;
    }
    __syncthreads();

    const int lane = tid & 31;
    const int w    = tid >> 5;
    const int g = lane >> 2;
    const int t = lane & 3;

    float acc0[NT][4], acc1[NT][4];
    #pragma unroll
    for (int nt = 0; nt < NT; nt++)
        #pragma unroll
        for (int k = 0; k < 4; k++) { acc0[nt][k] = 0.f; acc1[nt][k] = 0.f; }

    // FULLY UNROLLED tap loop: offsets constant-fold into LDS immediates.
    {
        const unsigned* tbase = tile + (2 * w * TW + g) * PW + 4 * t;
        const unsigned* wbb   = sw1 + g * PW + 4 * t;
        #pragma unroll
        for (int tap = 0; tap < 9; tap++) {
            const int dy = tap / 3, dx = tap % 3;
            const int off = (dy * TW + dx) * PW;
            uint4 a0g = *(const uint4*)(tbase + off);
            uint4 a0h = *(const uint4*)(tbase + off + 8 * PW);
            uint4 a1g = *(const uint4*)(tbase + off + TW * PW);
            uint4 a1h = *(const uint4*)(tbase + off + (TW + 8) * PW);
            #pragma unroll
            for (int nt = 0; nt < NT; nt++) {
                uint4 wv = *(const uint4*)(wbb + (tap * COUT + nt * 8) * PW);
                mma_bf16(acc0[nt], a0g.x, a0h.x, a0g.y, a0h.y, wv.x, wv.y);
                mma_bf16(acc0[nt], a0g.z, a0h.z, a0g.w, a0h.w, wv.z, wv.w);
                mma_bf16(acc1[nt], a1g.x, a1h.x, a1g.y, a1h.y, wv.x, wv.y);
                mma_bf16(acc1[nt], a1g.z, a1h.z, a1g.w, a1h.w, wv.z, wv.w);
            }
        }
    }

    // ---- chain: D fragments -> A fragments in registers -------------------
    #pragma unroll
    for (int rr = 0; rr < 2; rr++) {
        float (*acc)[4] = rr ? acc1 : acc0;

        unsigned afr[4][4];
        #pragma unroll
        for (int kb = 0; kb < 4; kb++) {
            int oc0 = kb * 16 + 2 * t;
            int oc1 = oc0 + 8;
            float b00 = sb1[oc0], b01 = sb1[oc0 + 1];
            float b10 = sb1[oc1], b11 = sb1[oc1 + 1];
            afr[kb][0] = bf2(fmaxf(acc[2*kb][0]+b00, 0.f), fmaxf(acc[2*kb][1]+b01, 0.f));
            afr[kb][1] = bf2(fmaxf(acc[2*kb][2]+b00, 0.f), fmaxf(acc[2*kb][3]+b01, 0.f));
            afr[kb][2] = bf2(fmaxf(acc[2*kb+1][0]+b10, 0.f), fmaxf(acc[2*kb+1][1]+b11, 0.f));
            afr[kb][3] = bf2(fmaxf(acc[2*kb+1][2]+b10, 0.f), fmaxf(acc[2*kb+1][3]+b11, 0.f));
        }
        float hacc[8][4];
        #pragma unroll
        for (int nt = 0; nt < 8; nt++)
            #pragma unroll
            for (int k = 0; k < 4; k++) hacc[nt][k] = 0.f;
        #pragma unroll
        for (int grp = 0; grp < 2; grp++) {
            #pragma unroll
            for (int nt = 0; nt < 8; nt++) {
                uint4 wv = *(const uint4*)(sw2 + (nt * 8 + g) * PWF + grp * 16 + 4 * t);
                mma_bf16(hacc[nt], afr[2*grp][0], afr[2*grp][1], afr[2*grp][2], afr[2*grp][3],
                         wv.x, wv.y);
                mma_bf16(hacc[nt], afr[2*grp+1][0], afr[2*grp+1][1], afr[2*grp+1][2], afr[2*grp+1][3],
                         wv.z, wv.w);
            }
        }
        unsigned hfr[4][4];
        #pragma unroll
        for (int kb = 0; kb < 4; kb++) {
            int oc0 = kb * 16 + 2 * t;
            int oc1 = oc0 + 8;
            float b00 = sb2[oc0], b01 = sb2[oc0 + 1];
            float b10 = sb2[oc1], b11 = sb2[oc1 + 1];
            hfr[kb][0] = bf2(fmaxf(hacc[2*kb][0]+b00, 0.f), fmaxf(hacc[2*kb][1]+b01, 0.f));
            hfr[kb][1] = bf2(fmaxf(hacc[2*kb][2]+b00, 0.f), fmaxf(hacc[2*kb][3]+b01, 0.f));
            hfr[kb][2] = bf2(fmaxf(hacc[2*kb+1][0]+b10, 0.f), fmaxf(hacc[2*kb+1][1]+b11, 0.f));
            hfr[kb][3] = bf2(fmaxf(hacc[2*kb+1][2]+b10, 0.f), fmaxf(hacc[2*kb+1][3]+b11, 0.f));
        }
        float g3[2][4];
        #pragma unroll
        for (int nt = 0; nt < 2; nt++)
            #pragma unroll
            for (int k = 0; k < 4; k++) g3[nt][k] = 0.f;
        #pragma unroll
        for (int grp = 0; grp < 2; grp++) {
            #pragma unroll
            for (int nt = 0; nt < 2; nt++) {
                uint4 wv = *(const uint4*)(sw3 + (nt * 8 + g) * PWF + grp * 16 + 4 * t);
                mma_bf16(g3[nt], hfr[2*grp][0], hfr[2*grp][1], hfr[2*grp][2], hfr[2*grp][3],
                         wv.x, wv.y);
                mma_bf16(g3[nt], hfr[2*grp+1][0], hfr[2*grp+1][1], hfr[2*grp+1][2], hfr[2*grp+1][3],
                         wv.z, wv.w);
            }
        }
        float o0a = 0.f, o1a = 0.f, o0b = 0.f, o1b = 0.f;
        #pragma unroll
        for (int nt = 0; nt < 2; nt++) {
            #pragma unroll
            for (int p = 0; p < 2; p++) {
                int col = nt * 8 + 2 * t + p;
                float bi = sb3[col];
                float w0 = sw4f[col * 2], w1 = sw4f[col * 2 + 1];
                float va = fmaxf(g3[nt][p] + bi, 0.f);
                float vb = fmaxf(g3[nt][2 + p] + bi, 0.f);
                o0a = fmaf(va, w0, o0a); o1a = fmaf(va, w1, o1a);
                o0b = fmaf(vb, w0, o0b); o1b = fmaf(vb, w1, o1b);
            }
        }
        #pragma unroll
        for (int m = 1; m <= 2; m <<= 1) {
            o0a += __shfl_xor_sync(0xffffffffu, o0a, m);
            o1a += __shfl_xor_sync(0xffffffffu, o1a, m);
            o0b += __shfl_xor_sync(0xffffffffu, o0b, m);
            o1b += __shfl_xor_sync(0xffffffffu, o1b, m);
        }

        const int gy = by + 2 * w + rr;
        const int xA = bx + g, xB = xA + 8;
        size_t pixA = (size_t)((b * HH + gy) * WW + xA);
        size_t pixB = pixA + 8;
        float2 fA = ((const float2*)flow)[pixA];
        float2 fB = ((const float2*)flow)[pixB];
        float fcAx = fA.x + o0a + sb4[0], fcAy = fA.y + o1a + sb4[1];
        float fcBx = fB.x + o0b + sb4[0], fcBy = fB.y + o1b + sb4[1];
        if (t == 0) {
            ((float2*)flowch)[pixA] = make_float2(fcAx, fcAy);
            ((float2*)flowch)[pixB] = make_float2(fcBx, fcBy);
        }
        float qyA = (float)gy - fcAx, qxA = (float)xA - fcAy;
        float fyA = fminf(fmaxf(floorf(qyA), 0.f), (float)(HH - 2));
        float fxA = fminf(fmaxf(floorf(qxA), 0.f), (float)(WW - 2));
        float ayA = fminf(fmaxf(qyA - fyA, 0.f), 1.f);
        float axA = fminf(fmaxf(qxA - fxA, 0.f), 1.f);
        int baseA = ((b * HH + (int)fyA) * WW + (int)fxA) * 8;

        float qyB = (float)gy - fcBx, qxB = (float)xB - fcBy;
        float fyB = fminf(fmaxf(floorf(qyB), 0.f), (float)(HH - 2));
        float fxB = fminf(fmaxf(floorf(qxB), 0.f), (float)(WW - 2));
        float ayB = fminf(fmaxf(qyB - fyB, 0.f), 1.f);
        float axB = fminf(fmaxf(qxB - fxB, 0.f), 1.f);
        int baseB = ((b * HH + (int)fyB) * WW + (int)fxB) * 8;

        const float4* s4 = (const float4*)srcimg;
        float4* oA = (float4*)outWarped + pixA * 8;
        float4* oB = (float4*)outWarped + pixB * 8;
        #pragma unroll
        for (int cc = 0; cc < 2; cc++) {
            int c4 = t * 2 + cc;
            oA[c4] = bilin4(s4, baseA + c4, ayA, axA);
            oB[c4] = bilin4(s4, baseB + c4, ayB, axB);
        }
    }
}

// ---------------- 2x bilinear upsample — both dirs in one launch ----------
__global__ __launch_bounds__(256) void upsample_kernel(
    const float* __restrict__ src, float* __restrict__ out)
{
    int idx = blockIdx.x * blockDim.x + threadIdx.x;
    int x = idx & 511;
    int y = (idx >> 9) & 511;
    int b = idx >> 18;
    float sy = 0.5f * (float)y - 0.25f;
    float sx = 0.5f * (float)x - 0.25f;
    float y0f = floorf(sy), x0f = floorf(sx);
    float wy = sy - y0f,    wx = sx - x0f;
    int y0 = (int)y0f, x0 = (int)x0f;
    int ya = max(y0, 0), yb = min(y0 + 1, HH - 1);
    int xa = max(x0, 0), xb = min(x0 + 1, WW - 1);
    const float2* s = (const float2*)src;
    float2 v00 = s[(b * HH + ya) * WW + xa];
    float2 v01 = s[(b * HH + ya) * WW + xb];
    float2 v10 = s[(b * HH + yb) * WW + xa];
    float2 v11 = s[(b * HH + yb) * WW + xb];
    float2 r;
    r.x = (1.f - wy) * ((1.f - wx) * v00.x + wx * v01.x)
        +        wy  * ((1.f - wx) * v10.x + wx * v11.x);
    r.y = (1.f - wy) * ((1.f - wx) * v00.y + wx * v01.y)
        +        wy  * ((1.f - wx) * v10.y + wx * v11.y);
    ((float2*)out)[idx] = r;
}

// ---------------- launch ---------------------------------------------------
extern "C" void kernel_launch(void* const* d_in, const int* in_sizes, int n_in,
                              void* d_out, int out_size)
{
    (void)in_sizes; (void)n_in; (void)out_size;
    const float* input_1 = (const float*)d_in[0];
    const float* input_2 = (const float*)d_in[1];
    const float* flow12  = (const float*)d_in[2];
    const float* flow21  = (const float*)d_in[3];
    float* out = (float*)d_out;

    unsigned *c0w, *wpack;
    float *flowch, *bpack;
    cudaGetSymbolAddress((void**)&c0w,    g_c0_w);
    cudaGetSymbolAddress((void**)&flowch, g_flowch);
    cudaGetSymbolAddress((void**)&wpack,  g_wpack);
    cudaGetSymbolAddress((void**)&bpack,  g_bpack);

    const int SM_CONV0 = (18 * 18 * 32 + WPW_N0) * 4 + 32 * 4;
    const int SM_MEGA  = (18 * 18 * 16 + WPW_N1 + WPW_F2 + WPW_F3) * 4 + 256 * 4;
    cudaFuncSetAttribute(conv0_tc_kernel,
                         cudaFuncAttributeMaxDynamicSharedMemorySize, SM_CONV0);
    cudaFuncSetAttribute(conv1_mega_kernel,
                         cudaFuncAttributeMaxDynamicSharedMemorySize, SM_MEGA);

    const float* w[2][5];
    const float* bw[2][5];
    for (int dir = 0; dir < 2; dir++)
        for (int i = 0; i < 5; i++) {
            w[dir][i]  = (const float*)d_in[4 + 4 * i + 2 * dir];
            bw[dir][i] = (const float*)d_in[4 + 4 * i + 2 * dir + 1];
        }

    {
        const int total = 2 * WPW_PER;
        prepack_kernel<<<(total + 255) / 256, 256>>>(
            w[0][0], w[0][1], w[0][2], w[0][3],
            w[1][0], w[1][1], w[1][2], w[1][3], wpack);
        biaspack_kernel<<<2, 256>>>(
            bw[0][0], bw[0][1], bw[0][2], bw[0][3], w[0][4], bw[0][4],
            bw[1][0], bw[1][1], bw[1][2], bw[1][3], w[1][4], bw[1][4], bpack);
    }

    dim3 grid(WW / 16, HH / 16, 2 * BB);

    conv0_tc_kernel<<<grid, 256, SM_CONV0>>>(
        input_1, input_2, flow12, flow21, wpack, bpack, c0w);
    conv1_mega_kernel<<<grid, 256, SM_MEGA>>>(
        c0w, input_1, input_2, flow12, flow21, wpack, bpack, out, flowch);
    upsample_kernel<<<2 * BB * 512 * 512 / 256, 256>>>(
        flowch, out + 2ull * NPIXTOT * 32);
}

// round 17
// speedup vs baseline: 1.1075x; 1.0109x over previous
#include <cuda_runtime.h>
#include <cuda_bf16.h>

#define BB 8
#define HH 256
#define WW 256
#define NPIXTOT (BB*HH*WW)

typedef unsigned long long ull;

// ---------------- bf16 helpers ---------------------------------------------
__device__ __forceinline__ unsigned bf2(float lo, float hi) {
    __nv_bfloat162 h = __floats2bfloat162_rn(lo, hi);
    return *(unsigned*)&h;
}
__device__ __forceinline__ void mma_bf16(float* c,
    unsigned a0, unsigned a1, unsigned a2, unsigned a3,
    unsigned b0, unsigned b1)
{
    asm("mma.sync.aligned.m16n8k16.row.col.f32.bf16.bf16.f32 "
        "{%0,%1,%2,%3}, {%4,%5,%6,%7}, {%8,%9}, {%0,%1,%2,%3};"
        : "+f"(c[0]), "+f"(c[1]), "+f"(c[2]), "+f"(c[3])
        : "r"(a0), "r"(a1), "r"(a2), "r"(a3), "r"(b0), "r"(b1));
}

// ---------------- packed f32x2 lerp (bit-identical to FADD+FFMA) ------------
__device__ __forceinline__ ull ffma2(ull a, ull b, ull c) {
    ull d;
    asm("fma.rn.f32x2 %0, %1, %2, %3;" : "=l"(d) : "l"(a), "l"(b), "l"(c));
    return d;
}
__device__ __forceinline__ ull packf2(float lo, float hi) {
    ull d;
    asm("mov.b64 %0, {%1, %2};" : "=l"(d) : "f"(lo), "f"(hi));
    return d;
}
#define NEG1X2 0xBF800000BF800000ull
// a + t*(b-a), per 32-bit lane; rounding identical to scalar (b-a exact FMA)
__device__ __forceinline__ ull lerp2(ull a, ull b, ull t2) {
    return ffma2(ffma2(a, NEG1X2, b), t2, a);
}

// QUAD-PAIR layout: within a 32-channel group (16 bf16-pair words), pair q
// (channels 2q,2q+1) lives at word  w(q) = (q&3)*4 + ((q>>2)&1) + ((q&8)?2:0).

// ---------------- scratch (device globals; no allocation allowed) ----------
__device__ unsigned g_c0_w[2ull * NPIXTOT * 16];   // conv0 out (quad-pair)
__device__ float    g_flowch[2ull * NPIXTOT * 2];

#define PWF 48
#define WPW_N0 (9*32*32)
#define WPW_N1 (9*64*16)
#define WPW_F2 (64*PWF)
#define WPW_F3 (16*PWF)
#define WPW_PER (WPW_N0 + WPW_N1 + WPW_F2 + WPW_F3)
__device__ unsigned g_wpack[2 * WPW_PER];
#define BP_PER 256
__device__ float g_bpack[2 * BP_PER];

// ---------------- weight prepack -------------------------------------------
__global__ void prepack_kernel(
    const float* __restrict__ c0d0, const float* __restrict__ c1d0,
    const float* __restrict__ w2d0, const float* __restrict__ w3d0,
    const float* __restrict__ c0d1, const float* __restrict__ c1d1,
    const float* __restrict__ w2d1, const float* __restrict__ w3d1,
    unsigned* __restrict__ dst)
{
    int i = blockIdx.x * blockDim.x + threadIdx.x;
    if (i >= 2 * WPW_PER) return;
    int dir = (i >= WPW_PER);
    int j = i - dir * WPW_PER;
    float lo = 0.f, hi = 0.f;
    if (j < WPW_N0) {
        const float* w = dir ? c0d1 : c0d0;           // [tap][64][32]
        int row = j / 32, pw = j % 32;
        int lw = pw ^ ((row & 1) << 4);
        int grp = lw >> 4, w16 = lw & 15;
        int t = w16 >> 2, slot = w16 & 1, kbs = (w16 >> 1) & 1;
        int q = t + slot * 4 + kbs * 8;
        int ch = grp * 32 + 2 * q;
        int oc = row % 32, tap = row / 32;
        lo = w[(tap * 64 + ch) * 32 + oc];
        hi = w[(tap * 64 + ch + 1) * 32 + oc];
    } else if (j < WPW_N0 + WPW_N1) {
        j -= WPW_N0;
        const float* w = dir ? c1d1 : c1d0;           // [tap][32][64]
        int row = j / 16, w16 = j % 16;
        int t = w16 >> 2, slot = w16 & 1, kbs = (w16 >> 1) & 1;
        int ch = 2 * (t + slot * 4 + kbs * 8);
        int oc = row % 64, tap = row / 64;
        lo = w[(tap * 32 + ch) * 64 + oc];
        hi = w[(tap * 32 + ch + 1) * 64 + oc];
    } else if (j < WPW_N0 + WPW_N1 + WPW_F2) {
        j -= WPW_N0 + WPW_N1;
        const float* w = dir ? w2d1 : w2d0;           // [64][64]
        int oc = j / PWF, pw = j % PWF;
        if (pw < 32) {
            int grp = pw >> 4, w16 = pw & 15;
            int t = w16 >> 2, slot = w16 & 1, kbs = (w16 >> 1) & 1;
            int ch = grp * 32 + 2 * (t + slot * 4 + kbs * 8);
            lo = w[ch * 64 + oc];
            hi = w[(ch + 1) * 64 + oc];
        }
    } else {
        j -= WPW_N0 + WPW_N1 + WPW_F2;
        const float* w = dir ? w3d1 : w3d0;           // [64][16]
        int oc = j / PWF, pw = j % PWF;
        if (pw < 32) {
            int grp = pw >> 4, w16 = pw & 15;
            int t = w16 >> 2, slot = w16 & 1, kbs = (w16 >> 1) & 1;
            int ch = grp * 32 + 2 * (t + slot * 4 + kbs * 8);
            lo = w[ch * 16 + oc];
            hi = w[(ch + 1) * 16 + oc];
        }
    }
    dst[i] = bf2(lo, hi);
}

__global__ void biaspack_kernel(
    const float* __restrict__ b0d0, const float* __restrict__ b1d0,
    const float* __restrict__ b2d0, const float* __restrict__ b3d0,
    const float* __restrict__ w4d0, const float* __restrict__ b4d0,
    const float* __restrict__ b0d1, const float* __restrict__ b1d1,
    const float* __restrict__ b2d1, const float* __restrict__ b3d1,
    const float* __restrict__ w4d1, const float* __restrict__ b4d1,
    float* __restrict__ dst)
{
    int i = threadIdx.x;
    int dir = blockIdx.x;
    const float* srcs[6] = {
        dir ? b0d1 : b0d0, dir ? b1d1 : b1d0, dir ? b2d1 : b2d0,
        dir ? b3d1 : b3d0, dir ? w4d1 : w4d0, dir ? b4d1 : b4d0 };
    const int offs[7] = {0, 32, 96, 160, 176, 208, 210};
    float v = 0.f;
    #pragma unroll
    for (int s = 0; s < 6; s++)
        if (i >= offs[s] && i < offs[s + 1]) v = srcs[s][i - offs[s]];
    dst[dir * BP_PER + i] = v;
}

// ---------------- packed bilinear 4-channel gather (fp32 src) ---------------
__device__ __forceinline__ float4 bilin4(const float4* s4, int base,
                                         ull ay2, ull ax2)
{
    ulonglong2 tl = *(const ulonglong2*)(s4 + base);
    ulonglong2 tr = *(const ulonglong2*)(s4 + base + 8);
    ulonglong2 bl = *(const ulonglong2*)(s4 + base + WW * 8);
    ulonglong2 br = *(const ulonglong2*)(s4 + base + WW * 8 + 8);
    ulonglong2 top, bot, r;
    top.x = lerp2(tl.x, tr.x, ax2);
    top.y = lerp2(tl.y, tr.y, ax2);
    bot.x = lerp2(bl.x, br.x, ax2);
    bot.y = lerp2(bl.y, br.y, ax2);
    r.x = lerp2(top.x, bot.x, ay2);
    r.y = lerp2(top.y, bot.y, ay2);
    float4 o;
    *(ulonglong2*)&o = r;
    return o;
}

// ---------------- conv0: 64->32, tile 16x16, fused warp+concat, quad-pair ---
__global__ __launch_bounds__(256, 2) void conv0_tc_kernel(
    const float* __restrict__ input_1, const float* __restrict__ input_2,
    const float* __restrict__ flow12, const float* __restrict__ flow21,
    const unsigned* __restrict__ wpackg, const float* __restrict__ bpackg,
    unsigned* __restrict__ c0wg)
{
    constexpr int COUT = 32;
    constexpr int TX = 16, TY = 16;
    constexpr int TW = TX + 2, TH = TY + 2;
    constexpr int PW = 32;
    constexpr int NT = COUT / 8;          // 4
    constexpr int TILE_W = TH * TW * PW;

    extern __shared__ unsigned smw[];
    unsigned* tile = smw;
    unsigned* sw   = smw + TILE_W;
    float*    sb   = (float*)(sw + WPW_N0);

    const int dir = blockIdx.z >> 3;
    const int b   = blockIdx.z & 7;
    const float* other  = dir ? input_1 : input_2;
    const float* srcimg = dir ? input_2 : input_1;
    const float* flow   = dir ? flow21 : flow12;
    const unsigned* wpack = wpackg + (size_t)dir * WPW_PER;
    const float* bias = bpackg + dir * BP_PER;
    unsigned* outw = c0wg + (size_t)dir * NPIXTOT * 16;

    const int bx = blockIdx.x * TX;
    const int by = blockIdx.y * TY;
    const int tid = threadIdx.x;

    {
        const uint4* s4 = (const uint4*)wpack;
        uint4* d4 = (uint4*)sw;
        #pragma unroll 4
        for (int i = tid; i < WPW_N0 / 4; i += 256) d4[i] = s4[i];
        if (tid < COUT) sb[tid] = bias[tid];
    }
    for (int i = tid; i < TH * TW * 4; i += 256) {
        int kb = i & 3;
        int p  = i >> 2;
        int xx = p % TW;
        int yy = p / TW;
        int gx = bx + xx - 1;
        int gy = by + yy - 1;
        float4 v[4];
        v[0] = v[1] = v[2] = v[3] = make_float4(0.f, 0.f, 0.f, 0.f);
        if (gx >= 0 && gx < WW && gy >= 0 && gy < HH) {
            int pix = (b * HH + gy) * WW + gx;
            if (kb < 2) {
                const float4* s = (const float4*)other + (size_t)pix * 8 + kb * 4;
                v[0] = s[0]; v[1] = s[1]; v[2] = s[2]; v[3] = s[3];
            } else {
                float2 f = ((const float2*)flow)[pix];
                float qy = (float)gy - f.x;
                float qx = (float)gx - f.y;
                float fy = fminf(fmaxf(floorf(qy), 0.f), (float)(HH - 2));
                float fx = fminf(fmaxf(floorf(qx), 0.f), (float)(WW - 2));
                float ay = fminf(fmaxf(qy - fy, 0.f), 1.f);
                float ax = fminf(fmaxf(qx - fx, 0.f), 1.f);
                ull ay2 = packf2(ay, ay), ax2 = packf2(ax, ax);
                int iy = (int)fy, ix = (int)fx;
                const float4* s4 = (const float4*)srcimg;
                int base = ((b * HH + iy) * WW + ix) * 8 + (kb - 2) * 4;
                #pragma unroll
                for (int jj = 0; jj < 4; jj++)
                    v[jj] = bilin4(s4, base + jj, ay2, ax2);
            }
        }
        int grp = kb >> 1, kbs = kb & 1;
        unsigned base = p * PW + ((grp * 16) ^ ((p & 1) << 4)) + kbs * 2;
        float2 pv[8];
        pv[0] = make_float2(v[0].x, v[0].y);
        pv[1] = make_float2(v[0].z, v[0].w);
        pv[2] = make_float2(v[1].x, v[1].y);
        pv[3] = make_float2(v[1].z, v[1].w);
        pv[4] = make_float2(v[2].x, v[2].y);
        pv[5] = make_float2(v[2].z, v[2].w);
        pv[6] = make_float2(v[3].x, v[3].y);
        pv[7] = make_float2(v[3].z, v[3].w);
        #pragma unroll
        for (int t2 = 0; t2 < 4; t2++) {
            uint2 wv = make_uint2(bf2(pv[t2].x, pv[t2].y),
                                  bf2(pv[t2 + 4].x, pv[t2 + 4].y));
            *(uint2*)(tile + base + t2 * 4) = wv;
        }
    }
    __syncthreads();

    const int lane = tid & 31;
    const int w    = tid >> 5;
    const int g = lane >> 2;
    const int t = lane & 3;

    float acc0[NT][4], acc1[NT][4];
    #pragma unroll
    for (int nt = 0; nt < NT; nt++)
        #pragma unroll
        for (int k = 0; k < 4; k++) { acc0[nt][k] = 0.f; acc1[nt][k] = 0.f; }

    const unsigned wswz = (g & 1) << 4;

    #pragma unroll
    for (int tap = 0; tap < 9; tap++) {
        const int dy = tap / 3, dx = tap % 3;
        const int p0 = (2 * w + dy) * TW + dx;
        uint4 a0g[2], a0h[2], a1g[2], a1h[2];
        #pragma unroll
        for (int grp = 0; grp < 2; grp++) {
            int pa = p0 + g;
            a0g[grp] = *(const uint4*)(tile + pa * PW + ((grp * 16 + 4 * t) ^ ((pa & 1) << 4)));
            int pb = p0 + g + 8;
            a0h[grp] = *(const uint4*)(tile + pb * PW + ((grp * 16 + 4 * t) ^ ((pb & 1) << 4)));
            int pc = p0 + TW + g;
            a1g[grp] = *(const uint4*)(tile + pc * PW + ((grp * 16 + 4 * t) ^ ((pc & 1) << 4)));
            int pd = p0 + TW + g + 8;
            a1h[grp] = *(const uint4*)(tile + pd * PW + ((grp * 16 + 4 * t) ^ ((pd & 1) << 4)));
        }
        const unsigned* wb = sw + tap * COUT * PW;
        #pragma unroll
        for (int nt = 0; nt < NT; nt++) {
            const unsigned* wr = wb + (nt * 8 + g) * PW;
            #pragma unroll
            for (int grp = 0; grp < 2; grp++) {
                uint4 wv = *(const uint4*)(wr + ((grp * 16 + 4 * t) ^ wswz));
                mma_bf16(acc0[nt], a0g[grp].x, a0h[grp].x, a0g[grp].y, a0h[grp].y, wv.x, wv.y);
                mma_bf16(acc0[nt], a0g[grp].z, a0h[grp].z, a0g[grp].w, a0h[grp].w, wv.z, wv.w);
                mma_bf16(acc1[nt], a1g[grp].x, a1h[grp].x, a1g[grp].y, a1h[grp].y, wv.x, wv.y);
                mma_bf16(acc1[nt], a1g[grp].z, a1h[grp].z, a1g[grp].w, a1h[grp].w, wv.z, wv.w);
            }
        }
    }

    #pragma unroll
    for (int rr = 0; rr < 2; rr++) {
        const int gy = by + 2 * w + rr;
        float (*acc)[4] = rr ? acc1 : acc0;
        size_t pix0 = (size_t)((b * HH + gy) * WW + bx + g);
        unsigned* o0 = outw + pix0 * 16;
        unsigned* o1 = o0 + 8 * 16;
        #pragma unroll
        for (int nt = 0; nt < NT; nt++) {
            int oc = nt * 8 + 2 * t;
            int q = nt * 4 + t;
            int word = (q & 3) * 4 + ((q >> 2) & 1) + ((q & 8) ? 2 : 0);
            float bi0 = sb[oc], bi1 = sb[oc + 1];
            o0[word] = bf2(fmaxf(acc[nt][0] + bi0, 0.f), fmaxf(acc[nt][1] + bi1, 0.f));
            o1[word] = bf2(fmaxf(acc[nt][2] + bi0, 0.f), fmaxf(acc[nt][3] + bi1, 0.f));
        }
    }
}

// ---------------- MEGA: conv1 + 1x1 chain + flow add + final warp ----------
__global__ __launch_bounds__(256, 2) void conv1_mega_kernel(
    const unsigned* __restrict__ c0wg,
    const float* __restrict__ input_1, const float* __restrict__ input_2,
    const float* __restrict__ flow12, const float* __restrict__ flow21,
    const unsigned* __restrict__ wpackg, const float* __restrict__ bpackg,
    float* __restrict__ outAll, float* __restrict__ flowchg)
{
    constexpr int COUT = 64;
    constexpr int TX = 16, TY = 16;
    constexpr int TW = TX + 2, TH = TY + 2;
    constexpr int PW = 16;
    constexpr int NT = COUT / 8;          // 8
    constexpr int TILE_W = TH * TW * PW;

    extern __shared__ unsigned smw[];
    unsigned* tile = smw;
    unsigned* sw1  = smw + TILE_W;
    unsigned* sw2  = sw1 + WPW_N1;
    unsigned* sw3  = sw2 + WPW_F2;
    float*    sbf  = (float*)(sw3 + WPW_F3);

    const int dir = blockIdx.z >> 3;
    const int b   = blockIdx.z & 7;
    const float* srcimg = dir ? input_2 : input_1;
    const float* flow = dir ? flow21 : flow12;
    const unsigned* wbase = wpackg + (size_t)dir * WPW_PER;
    const unsigned* in = c0wg + (size_t)dir * NPIXTOT * 16;
    float* flowch = flowchg + (size_t)dir * NPIXTOT * 2;
    float* outWarped = outAll + (size_t)dir * NPIXTOT * 32;

    float* sb1  = sbf + 32;
    float* sb2  = sbf + 96;
    float* sb3  = sbf + 160;
    float* sw4f = sbf + 176;
    float* sb4  = sbf + 208;

    const int bx = blockIdx.x * TX;
    const int by = blockIdx.y * TY;
    const int tid = threadIdx.x;

    {
        const uint4* s1 = (const uint4*)(wbase + WPW_N0);
        uint4* d1 = (uint4*)sw1;
        #pragma unroll 4
        for (int i = tid; i < (WPW_N1 + WPW_F2 + WPW_F3) / 4; i += 256) d1[i] = s1[i];
        sbf[tid] = bpackg[dir * BP_PER + tid];
    }
    for (int i = tid; i < TH * TW * 4; i += 256) {
        int q = i & 3;
        int p = i >> 2;
        int xx = p % TW;
        int yy = p / TW;
        int gx = bx + xx - 1;
        int gy = by + yy - 1;
        uint4 v = make_uint4(0, 0, 0, 0);
        if (gx >= 0 && gx < WW && gy >= 0 && gy < HH) {
            size_t pix = (size_t)((b * HH + gy) * WW + gx);
            v = *(const uint4*)(in + pix * 16 + q * 4);
        }
        *(uint4*)(tile + p * PW + q * 4) = v;
    }
    __syncthreads();

    const int lane = tid & 31;
    const int w    = tid >> 5;
    const int g = lane >> 2;
    const int t = lane & 3;

    float acc0[NT][4], acc1[NT][4];
    #pragma unroll
    for (int nt = 0; nt < NT; nt++)
        #pragma unroll
        for (int k = 0; k < 4; k++) { acc0[nt][k] = 0.f; acc1[nt][k] = 0.f; }

    {
        const unsigned* tbase = tile + (2 * w * TW + g) * PW + 4 * t;
        const unsigned* wbb   = sw1 + g * PW + 4 * t;
        #pragma unroll
        for (int tap = 0; tap < 9; tap++) {
            const int dy = tap / 3, dx = tap % 3;
            const int off = (dy * TW + dx) * PW;
            uint4 a0g = *(const uint4*)(tbase + off);
            uint4 a0h = *(const uint4*)(tbase + off + 8 * PW);
            uint4 a1g = *(const uint4*)(tbase + off + TW * PW);
            uint4 a1h = *(const uint4*)(tbase + off + (TW + 8) * PW);
            #pragma unroll
            for (int nt = 0; nt < NT; nt++) {
                uint4 wv = *(const uint4*)(wbb + (tap * COUT + nt * 8) * PW);
                mma_bf16(acc0[nt], a0g.x, a0h.x, a0g.y, a0h.y, wv.x, wv.y);
                mma_bf16(acc0[nt], a0g.z, a0h.z, a0g.w, a0h.w, wv.z, wv.w);
                mma_bf16(acc1[nt], a1g.x, a1h.x, a1g.y, a1h.y, wv.x, wv.y);
                mma_bf16(acc1[nt], a1g.z, a1h.z, a1g.w, a1h.w, wv.z, wv.w);
            }
        }
    }

    // ---- chain: D fragments -> A fragments in registers -------------------
    #pragma unroll
    for (int rr = 0; rr < 2; rr++) {
        float (*acc)[4] = rr ? acc1 : acc0;

        unsigned afr[4][4];
        #pragma unroll
        for (int kb = 0; kb < 4; kb++) {
            int oc0 = kb * 16 + 2 * t;
            int oc1 = oc0 + 8;
            float b00 = sb1[oc0], b01 = sb1[oc0 + 1];
            float b10 = sb1[oc1], b11 = sb1[oc1 + 1];
            afr[kb][0] = bf2(fmaxf(acc[2*kb][0]+b00, 0.f), fmaxf(acc[2*kb][1]+b01, 0.f));
            afr[kb][1] = bf2(fmaxf(acc[2*kb][2]+b00, 0.f), fmaxf(acc[2*kb][3]+b01, 0.f));
            afr[kb][2] = bf2(fmaxf(acc[2*kb+1][0]+b10, 0.f), fmaxf(acc[2*kb+1][1]+b11, 0.f));
            afr[kb][3] = bf2(fmaxf(acc[2*kb+1][2]+b10, 0.f), fmaxf(acc[2*kb+1][3]+b11, 0.f));
        }
        float hacc[8][4];
        #pragma unroll
        for (int nt = 0; nt < 8; nt++)
            #pragma unroll
            for (int k = 0; k < 4; k++) hacc[nt][k] = 0.f;
        #pragma unroll
        for (int grp = 0; grp < 2; grp++) {
            #pragma unroll
            for (int nt = 0; nt < 8; nt++) {
                uint4 wv = *(const uint4*)(sw2 + (nt * 8 + g) * PWF + grp * 16 + 4 * t);
                mma_bf16(hacc[nt], afr[2*grp][0], afr[2*grp][1], afr[2*grp][2], afr[2*grp][3],
                         wv.x, wv.y);
                mma_bf16(hacc[nt], afr[2*grp+1][0], afr[2*grp+1][1], afr[2*grp+1][2], afr[2*grp+1][3],
                         wv.z, wv.w);
            }
        }
        unsigned hfr[4][4];
        #pragma unroll
        for (int kb = 0; kb < 4; kb++) {
            int oc0 = kb * 16 + 2 * t;
            int oc1 = oc0 + 8;
            float b00 = sb2[oc0], b01 = sb2[oc0 + 1];
            float b10 = sb2[oc1], b11 = sb2[oc1 + 1];
            hfr[kb][0] = bf2(fmaxf(hacc[2*kb][0]+b00, 0.f), fmaxf(hacc[2*kb][1]+b01, 0.f));
            hfr[kb][1] = bf2(fmaxf(hacc[2*kb][2]+b00, 0.f), fmaxf(hacc[2*kb][3]+b01, 0.f));
            hfr[kb][2] = bf2(fmaxf(hacc[2*kb+1][0]+b10, 0.f), fmaxf(hacc[2*kb+1][1]+b11, 0.f));
            hfr[kb][3] = bf2(fmaxf(hacc[2*kb+1][2]+b10, 0.f), fmaxf(hacc[2*kb+1][3]+b11, 0.f));
        }
        float g3[2][4];
        #pragma unroll
        for (int nt = 0; nt < 2; nt++)
            #pragma unroll
            for (int k = 0; k < 4; k++) g3[nt][k] = 0.f;
        #pragma unroll
        for (int grp = 0; grp < 2; grp++) {
            #pragma unroll
            for (int nt = 0; nt < 2; nt++) {
                uint4 wv = *(const uint4*)(sw3 + (nt * 8 + g) * PWF + grp * 16 + 4 * t);
                mma_bf16(g3[nt], hfr[2*grp][0], hfr[2*grp][1], hfr[2*grp][2], hfr[2*grp][3],
                         wv.x, wv.y);
                mma_bf16(g3[nt], hfr[2*grp+1][0], hfr[2*grp+1][1], hfr[2*grp+1][2], hfr[2*grp+1][3],
                         wv.z, wv.w);
            }
        }
        float o0a = 0.f, o1a = 0.f, o0b = 0.f, o1b = 0.f;
        #pragma unroll
        for (int nt = 0; nt < 2; nt++) {
            #pragma unroll
            for (int p = 0; p < 2; p++) {
                int col = nt * 8 + 2 * t + p;
                float bi = sb3[col];
                float w0 = sw4f[col * 2], w1 = sw4f[col * 2 + 1];
                float va = fmaxf(g3[nt][p] + bi, 0.f);
                float vb = fmaxf(g3[nt][2 + p] + bi, 0.f);
                o0a = fmaf(va, w0, o0a); o1a = fmaf(va, w1, o1a);
                o0b = fmaf(vb, w0, o0b); o1b = fmaf(vb, w1, o1b);
            }
        }
        #pragma unroll
        for (int m = 1; m <= 2; m <<= 1) {
            o0a += __shfl_xor_sync(0xffffffffu, o0a, m);
            o1a += __shfl_xor_sync(0xffffffffu, o1a, m);
            o0b += __shfl_xor_sync(0xffffffffu, o0b, m);
            o1b += __shfl_xor_sync(0xffffffffu, o1b, m);
        }

        const int gy = by + 2 * w + rr;
        const int xA = bx + g, xB = xA + 8;
        size_t pixA = (size_t)((b * HH + gy) * WW + xA);
        size_t pixB = pixA + 8;
        float2 fA = ((const float2*)flow)[pixA];
        float2 fB = ((const float2*)flow)[pixB];
        float fcAx = fA.x + o0a + sb4[0], fcAy = fA.y + o1a + sb4[1];
        float fcBx = fB.x + o0b + sb4[0], fcBy = fB.y + o1b + sb4[1];
        if (t == 0) {
            ((float2*)flowch)[pixA] = make_float2(fcAx, fcAy);
            ((float2*)flowch)[pixB] = make_float2(fcBx, fcBy);
        }
        float qyA = (float)gy - fcAx, qxA = (float)xA - fcAy;
        float fyA = fminf(fmaxf(floorf(qyA), 0.f), (float)(HH - 2));
        float fxA = fminf(fmaxf(floorf(qxA), 0.f), (float)(WW - 2));
        float ayA = fminf(fmaxf(qyA - fyA, 0.f), 1.f);
        float axA = fminf(fmaxf(qxA - fxA, 0.f), 1.f);
        ull ayA2 = packf2(ayA, ayA), axA2 = packf2(axA, axA);
        int baseA = ((b * HH + (int)fyA) * WW + (int)fxA) * 8;

        float qyB = (float)gy - fcBx, qxB = (float)xB - fcBy;
        float fyB = fminf(fmaxf(floorf(qyB), 0.f), (float)(HH - 2));
        float fxB = fminf(fmaxf(floorf(qxB), 0.f), (float)(WW - 2));
        float ayB = fminf(fmaxf(qyB - fyB, 0.f), 1.f);
        float axB = fminf(fmaxf(qxB - fxB, 0.f), 1.f);
        ull ayB2 = packf2(ayB, ayB), axB2 = packf2(axB, axB);
        int baseB = ((b * HH + (int)fyB) * WW + (int)fxB) * 8;

        const float4* s4 = (const float4*)srcimg;
        float4* oA = (float4*)outWarped + pixA * 8;
        float4* oB = (float4*)outWarped + pixB * 8;
        #pragma unroll
        for (int cc = 0; cc < 2; cc++) {
            int c4 = t * 2 + cc;
            oA[c4] = bilin4(s4, baseA + c4, ayA2, axA2);
            oB[c4] = bilin4(s4, baseB + c4, ayB2, axB2);
        }
    }
}

// ---------------- 2x bilinear upsample — both dirs in one launch ----------
__global__ __launch_bounds__(256) void upsample_kernel(
    const float* __restrict__ src, float* __restrict__ out)
{
    int idx = blockIdx.x * blockDim.x + threadIdx.x;
    int x = idx & 511;
    int y = (idx >> 9) & 511;
    int b = idx >> 18;
    float sy = 0.5f * (float)y - 0.25f;
    float sx = 0.5f * (float)x - 0.25f;
    float y0f = floorf(sy), x0f = floorf(sx);
    float wy = sy - y0f,    wx = sx - x0f;
    int y0 = (int)y0f, x0 = (int)x0f;
    int ya = max(y0, 0), yb = min(y0 + 1, HH - 1);
    int xa = max(x0, 0), xb = min(x0 + 1, WW - 1);
    const float2* s = (const float2*)src;
    float2 v00 = s[(b * HH + ya) * WW + xa];
    float2 v01 = s[(b * HH + ya) * WW + xb];
    float2 v10 = s[(b * HH + yb) * WW + xa];
    float2 v11 = s[(b * HH + yb) * WW + xb];
    float2 r;
    r.x = (1.f - wy) * ((1.f - wx) * v00.x + wx * v01.x)
        +        wy  * ((1.f - wx) * v10.x + wx * v11.x);
    r.y = (1.f - wy) * ((1.f - wx) * v00.y + wx * v01.y)
        +        wy  * ((1.f - wx) * v10.y + wx * v11.y);
    ((float2*)out)[idx] = r;
}

// ---------------- launch ---------------------------------------------------
extern "C" void kernel_launch(void* const* d_in, const int* in_sizes, int n_in,
                              void* d_out, int out_size)
{
    (void)in_sizes; (void)n_in; (void)out_size;
    const float* input_1 = (const float*)d_in[0];
    const float* input_2 = (const float*)d_in[1];
    const float* flow12  = (const float*)d_in[2];
    const float* flow21  = (const float*)d_in[3];
    float* out = (float*)d_out;

    unsigned *c0w, *wpack;
    float *flowch, *bpack;
    cudaGetSymbolAddress((void**)&c0w,    g_c0_w);
    cudaGetSymbolAddress((void**)&flowch, g_flowch);
    cudaGetSymbolAddress((void**)&wpack,  g_wpack);
    cudaGetSymbolAddress((void**)&bpack,  g_bpack);

    const int SM_CONV0 = (18 * 18 * 32 + WPW_N0) * 4 + 32 * 4;
    const int SM_MEGA  = (18 * 18 * 16 + WPW_N1 + WPW_F2 + WPW_F3) * 4 + 256 * 4;
    cudaFuncSetAttribute(conv0_tc_kernel,
                         cudaFuncAttributeMaxDynamicSharedMemorySize, SM_CONV0);
    cudaFuncSetAttribute(conv1_mega_kernel,
                         cudaFuncAttributeMaxDynamicSharedMemorySize, SM_MEGA);

    const float* w[2][5];
    const float* bw[2][5];
    for (int dir = 0; dir < 2; dir++)
        for (int i = 0; i < 5; i++) {
            w[dir][i]  = (const float*)d_in[4 + 4 * i + 2 * dir];
            bw[dir][i] = (const float*)d_in[4 + 4 * i + 2 * dir + 1];
        }

    {
        const int total = 2 * WPW_PER;
        prepack_kernel<<<(total + 255) / 256, 256>>>(
            w[0][0], w[0][1], w[0][2], w[0][3],
            w[1][0], w[1][1], w[1][2], w[1][3], wpack);
        biaspack_kernel<<<2, 256>>>(
            bw[0][0], bw[0][1], bw[0][2], bw[0][3], w[0][4], bw[0][4],
            bw[1][0], bw[1][1], bw[1][2], bw[1][3], w[1][4], bw[1][4], bpack);
    }

    dim3 grid(WW / 16, HH / 16, 2 * BB);

    conv0_tc_kernel<<<grid, 256, SM_CONV0>>>(
        input_1, input_2, flow12, flow21, wpack, bpack, c0w);
    conv1_mega_kernel<<<grid, 256, SM_MEGA>>>(
        c0w, input_1, input_2, flow12, flow21, wpack, bpack, out, flowch);
    upsample_kernel<<<2 * BB * 512 * 512 / 256, 256>>>(
        flowch, out + 2ull * NPIXTOT * 32);
}